// round 1
// baseline (speedup 1.0000x reference)
#include <cuda_runtime.h>
#include <math.h>

// Problem dims
#define BB   8
#define SS   1024
#define EE   512
#define II   1024
#define HH   4
#define DHH  256
#define KKC  4
#define BSR  (BB*SS)          // 8192 rows
#define EPS  1e-5f

// ---------------- scratch (static device memory; rewritten every call) ----------
__device__ float g_xn  [BSR*EE];          // 16 MB
__device__ float g_up  [BSR*2048];        // 64 MB (x_m = cols [0,1024), z = cols [1024,2048))
__device__ float g_cact[BSR*II];          // 32 MB
__device__ float g_q   [BSR*II];
__device__ float g_k   [BSR*II];
__device__ float g_v   [BSR*II];
__device__ float g_h   [BSR*II];
__device__ float g_x1  [BSR*EE];
__device__ float g_ipre[BB*HH*SS];
__device__ float g_fpre[BB*HH*SS];
__device__ float g_lfc [BB*HH*SS];

// ---------------- LayerNorm over E=512 ----------------
__global__ __launch_bounds__(256) void ln_kernel(const float* __restrict__ x,
                                                 const float* __restrict__ g,
                                                 const float* __restrict__ b,
                                                 float* __restrict__ y)
{
    int row = blockIdx.x;
    const float* xr = x + (size_t)row * EE;
    float s = 0.f, s2 = 0.f;
    for (int c = threadIdx.x; c < EE; c += 256) { float v = xr[c]; s += v; s2 += v*v; }
    __shared__ float sh[64];
    for (int o = 16; o; o >>= 1) {
        s  += __shfl_down_sync(0xffffffffu, s,  o);
        s2 += __shfl_down_sync(0xffffffffu, s2, o);
    }
    int wid = threadIdx.x >> 5, lane = threadIdx.x & 31;
    if (lane == 0) { sh[wid] = s; sh[32+wid] = s2; }
    __syncthreads();
    if (threadIdx.x == 0) {
        float ts = 0.f, ts2 = 0.f;
        for (int w = 0; w < 8; w++) { ts += sh[w]; ts2 += sh[32+w]; }
        sh[0] = ts; sh[32] = ts2;
    }
    __syncthreads();
    float mu  = sh[0]  * (1.f/EE);
    float var = sh[32] * (1.f/EE) - mu*mu;
    float rstd = rsqrtf(var + EPS);
    float* yr = y + (size_t)row * EE;
    for (int c = threadIdx.x; c < EE; c += 256)
        yr[c] = (xr[c] - mu) * rstd * g[c] + b[c];
}

// ---------------- Generic fp32 GEMM: C[M,N] = A[M,K] @ B[K,N] (+bias)(+res) ----
// 128x128 tile, BK=8, 256 threads, 8x8 per thread. All dims divide tiles evenly.
__global__ __launch_bounds__(256) void sgemm_kernel(
    const float* __restrict__ A, int lda,
    const float* __restrict__ B, int ldb,
    float* __restrict__ C, int ldc,
    int K,
    const float* __restrict__ bias,
    const float* __restrict__ res, int ldres)
{
    __shared__ float As[8][128];
    __shared__ float Bsm[8][128];
    int tid  = threadIdx.x;
    int row0 = blockIdx.y * 128;
    int col0 = blockIdx.x * 128;
    int a_row = tid >> 1;
    int a_col = (tid & 1) << 2;
    int b_row = tid >> 5;
    int b_col = (tid & 31) << 2;
    int tr = (tid >> 4) << 3;
    int tc = (tid & 15) << 3;
    float acc[8][8];
    #pragma unroll
    for (int i = 0; i < 8; i++)
        #pragma unroll
        for (int j = 0; j < 8; j++) acc[i][j] = 0.f;

    const float* Ap = A + (size_t)(row0 + a_row) * lda + a_col;
    const float* Bp = B + (size_t)b_row * ldb + col0 + b_col;

    for (int k0 = 0; k0 < K; k0 += 8) {
        float4 av = *(const float4*)(Ap + k0);
        As[a_col+0][a_row] = av.x;
        As[a_col+1][a_row] = av.y;
        As[a_col+2][a_row] = av.z;
        As[a_col+3][a_row] = av.w;
        float4 bv = *(const float4*)(Bp + (size_t)k0 * ldb);
        *(float4*)&Bsm[b_row][b_col] = bv;
        __syncthreads();
        #pragma unroll
        for (int k = 0; k < 8; k++) {
            float ra[8], rb[8];
            *(float4*)&ra[0] = *(const float4*)&As[k][tr];
            *(float4*)&ra[4] = *(const float4*)&As[k][tr+4];
            *(float4*)&rb[0] = *(const float4*)&Bsm[k][tc];
            *(float4*)&rb[4] = *(const float4*)&Bsm[k][tc+4];
            #pragma unroll
            for (int i = 0; i < 8; i++)
                #pragma unroll
                for (int j = 0; j < 8; j++)
                    acc[i][j] = fmaf(ra[i], rb[j], acc[i][j]);
        }
        __syncthreads();
    }
    #pragma unroll
    for (int i = 0; i < 8; i++) {
        size_t r = (size_t)(row0 + tr + i);
        #pragma unroll
        for (int j = 0; j < 8; j += 4) {
            int c = col0 + tc + j;
            float4 v;
            v.x = acc[i][j]; v.y = acc[i][j+1]; v.z = acc[i][j+2]; v.w = acc[i][j+3];
            if (bias) { v.x += bias[c]; v.y += bias[c+1]; v.z += bias[c+2]; v.w += bias[c+3]; }
            if (res) {
                float4 rv = *(const float4*)(res + r * ldres + c);
                v.x += rv.x; v.y += rv.y; v.z += rv.z; v.w += rv.w;
            }
            *(float4*)(C + r * ldc + c) = v;
        }
    }
}

// ---------------- causal depthwise conv (K=4) + SiLU -----------------
__global__ __launch_bounds__(256) void conv_silu_kernel(const float* __restrict__ cw,
                                                        const float* __restrict__ cb)
{
    int idx = blockIdx.x * 256 + threadIdx.x;    // [0, BSR*II)
    int c   = idx & (II - 1);
    int row = idx >> 10;                          // b*S + t
    int t   = row & (SS - 1);
    float acc = cb[c];
    const float* base = g_up + (size_t)row * 2048 + c;
    #pragma unroll
    for (int j = 0; j < KKC; j++) {
        int tt = t - (KKC - 1) + j;
        if (tt >= 0) acc += base[(j - (KKC - 1)) * 2048] * cw[j * II + c];
    }
    g_cact[idx] = acc / (1.f + __expf(-acc));
}

// ---------------- gate projections: ipre/fpre[b,h,t] ---------------------------
__global__ __launch_bounds__(256) void gates_kernel(const float* __restrict__ wi,
                                                    const float* __restrict__ bi,
                                                    const float* __restrict__ wf,
                                                    const float* __restrict__ bf)
{
    int row = blockIdx.x;                 // b*S + t
    const float* q = g_q + (size_t)row * II;
    const float* k = g_k + (size_t)row * II;
    const float* v = g_v + (size_t)row * II;
    float ai[HH] = {0,0,0,0}, af[HH] = {0,0,0,0};
    for (int d = threadIdx.x; d < II; d += 256) {
        float qv = q[d], kv = k[d], vv = v[d];
        const float* wiq = wi + (size_t)d * HH;
        const float* wik = wi + (size_t)(II + d) * HH;
        const float* wiv = wi + (size_t)(2*II + d) * HH;
        const float* wfq = wf + (size_t)d * HH;
        const float* wfk = wf + (size_t)(II + d) * HH;
        const float* wfv = wf + (size_t)(2*II + d) * HH;
        #pragma unroll
        for (int h2 = 0; h2 < HH; h2++) {
            ai[h2] += qv*wiq[h2] + kv*wik[h2] + vv*wiv[h2];
            af[h2] += qv*wfq[h2] + kv*wfk[h2] + vv*wfv[h2];
        }
    }
    __shared__ float red[64];
    int lane = threadIdx.x & 31, wid = threadIdx.x >> 5;
    #pragma unroll
    for (int s = 0; s < 8; s++) {
        float x = (s < 4) ? ai[s] : af[s-4];
        for (int o = 16; o; o >>= 1) x += __shfl_down_sync(0xffffffffu, x, o);
        if (lane == 0) red[s * 8 + wid] = x;
    }
    __syncthreads();
    if (threadIdx.x < 64) {
        float x = red[threadIdx.x];
        x += __shfl_down_sync(0xffffffffu, x, 4, 8);
        x += __shfl_down_sync(0xffffffffu, x, 2, 8);
        x += __shfl_down_sync(0xffffffffu, x, 1, 8);
        if ((threadIdx.x & 7) == 0) {
            int s = threadIdx.x >> 3;
            int b = row >> 10, t = row & (SS - 1);
            if (s < 4) g_ipre[((size_t)b*HH + s)     * SS + t] = x + bi[s];
            else       g_fpre[((size_t)b*HH + (s-4)) * SS + t] = x + bf[s-4];
        }
    }
}

// ---------------- log-sigmoid + inclusive cumsum over S -----------------
__global__ __launch_bounds__(1024) void cumsum_kernel()
{
    int bh = blockIdx.x;
    int t  = threadIdx.x;
    float f  = g_fpre[bh * SS + t];
    float lf = (f > 0.f) ? -log1pf(__expf(-f)) : f - log1pf(__expf(f));
    __shared__ float sc[SS];
    sc[t] = lf;
    __syncthreads();
    for (int off = 1; off < SS; off <<= 1) {
        float v = (t >= off) ? sc[t - off] : 0.f;
        __syncthreads();
        sc[t] += v;
        __syncthreads();
    }
    g_lfc[bh * SS + t] = sc[t];
}

// ---------------- fused causal mLSTM attention (flash-style) -------------------
// grid = (S/32 t-blocks, B*H). 256 threads: ty=tid/8 = t-row, tx=tid%8 owns
// d columns {tx, tx+8, ..., tx+248} and s columns {tx, tx+8, tx+16, tx+24}.
#define ATT_SMEM_FLOATS (32*256 + 32*257 + 32*256 + 32*33 + 64)
__global__ __launch_bounds__(256) void attn_kernel()
{
    extern __shared__ float sm[];
    float* q_sh  = sm;                 // [32][256]
    float* k_sh  = q_sh + 32*256;      // [32][257] (padded vs bank conflicts)
    float* v_sh  = k_sh + 32*257;      // [32][256]
    float* w_sh  = v_sh + 32*256;      // [32][33]
    float* lfc_s = w_sh + 32*33;       // [32]
    float* ipr_s = lfc_s + 32;         // [32]

    int tb = blockIdx.x, bh = blockIdx.y;
    int b = bh >> 2, h = bh & 3;
    int tid = threadIdx.x;
    int ty = tid >> 3, tx = tid & 7;
    int t0 = tb * 32;
    size_t qkvbase = ((size_t)b * SS) * II + h * DHH;

    // q tile (pre-scaled by DH^-0.5 = 1/16)
    for (int r = 0; r < 32; r++)
        q_sh[r*256 + tid] = g_q[qkvbase + (size_t)(t0 + r) * II + tid] * 0.0625f;

    int t_glob = t0 + ty;
    float lfc_t = g_lfc[bh * SS + t_glob];
    float m = -1e30f, ssum = 0.f;
    float acc[32];
    #pragma unroll
    for (int j = 0; j < 32; j++) acc[j] = 0.f;

    for (int sb = 0; sb <= tb; sb++) {
        int s0 = sb * 32;
        __syncthreads();
        for (int r = 0; r < 32; r++) {
            k_sh[r*257 + tid] = g_k[qkvbase + (size_t)(s0 + r) * II + tid];
            v_sh[r*256 + tid] = g_v[qkvbase + (size_t)(s0 + r) * II + tid];
        }
        if (tid < 32) {
            lfc_s[tid] = g_lfc [bh * SS + s0 + tid];
            ipr_s[tid] = g_ipre[bh * SS + s0 + tid];
        }
        __syncthreads();

        float dot0=0.f, dot1=0.f, dot2=0.f, dot3=0.f;
        const float* qr  = q_sh + ty*256;
        const float* k0p = k_sh + tx*257;
        #pragma unroll 8
        for (int d = 0; d < 256; d++) {
            float qv = qr[d];
            dot0 = fmaf(qv, k0p[d],          dot0);
            dot1 = fmaf(qv, k0p[ 8*257 + d], dot1);
            dot2 = fmaf(qv, k0p[16*257 + d], dot2);
            dot3 = fmaf(qv, k0p[24*257 + d], dot3);
        }
        float dots[4] = {dot0, dot1, dot2, dot3};
        float logd[4];
        float mb = -1e30f;
        #pragma unroll
        for (int u = 0; u < 4; u++) {
            int sl = tx + 8*u;
            bool valid = (s0 + sl) <= t_glob;
            float ld = valid ? (lfc_t - lfc_s[sl] + ipr_s[sl]) : -1e30f;
            logd[u] = ld;
            mb = fmaxf(mb, ld);
        }
        mb = fmaxf(mb, __shfl_xor_sync(0xffffffffu, mb, 1));
        mb = fmaxf(mb, __shfl_xor_sync(0xffffffffu, mb, 2));
        mb = fmaxf(mb, __shfl_xor_sync(0xffffffffu, mb, 4));
        float m_new = fmaxf(m, mb);
        float scale = __expf(m - m_new);
        float wsum = 0.f;
        #pragma unroll
        for (int u = 0; u < 4; u++) {
            float wv = __expf(logd[u] - m_new) * dots[u];
            w_sh[ty*33 + tx + 8*u] = wv;
            wsum += wv;
        }
        ssum = ssum * scale + wsum;
        m = m_new;
        __syncthreads();

        #pragma unroll
        for (int j = 0; j < 32; j++) acc[j] *= scale;
        for (int sl = 0; sl < 32; sl++) {
            float wv = w_sh[ty*33 + sl];
            const float* vr = v_sh + sl*256 + tx;
            #pragma unroll
            for (int j = 0; j < 32; j++)
                acc[j] = fmaf(wv, vr[8*j], acc[j]);
        }
    }
    ssum += __shfl_xor_sync(0xffffffffu, ssum, 1);
    ssum += __shfl_xor_sync(0xffffffffu, ssum, 2);
    ssum += __shfl_xor_sync(0xffffffffu, ssum, 4);
    float n   = fmaxf(fabsf(ssum), __expf(-m));
    float inv = 1.f / n;
    float* outp = g_h + qkvbase + (size_t)t_glob * II + tx;
    #pragma unroll
    for (int j = 0; j < 32; j++) outp[8*j] = acc[j] * inv;
}

// ---------------- per-head norm + gn_g + skip*c_act + *silu(z) -------------
__global__ __launch_bounds__(256) void headgate_kernel(const float* __restrict__ gn,
                                                       const float* __restrict__ sk)
{
    int row = blockIdx.x;
    int tid = threadIdx.x;      // exactly DH=256 threads
    __shared__ float sh[16];
    __shared__ float stat[2];
    size_t base = (size_t)row * II;
    for (int h = 0; h < HH; h++) {
        float v = g_h[base + h*DHH + tid];
        float s = v, s2 = v*v;
        for (int o = 16; o; o >>= 1) {
            s  += __shfl_down_sync(0xffffffffu, s,  o);
            s2 += __shfl_down_sync(0xffffffffu, s2, o);
        }
        int wid = tid >> 5, lane = tid & 31;
        if (lane == 0) { sh[wid] = s; sh[8+wid] = s2; }
        __syncthreads();
        if (tid == 0) {
            float ts = 0.f, ts2 = 0.f;
            for (int w = 0; w < 8; w++) { ts += sh[w]; ts2 += sh[8+w]; }
            stat[0] = ts * (1.f/DHH); stat[1] = ts2 * (1.f/DHH);
        }
        __syncthreads();
        float mu = stat[0];
        float var = stat[1] - mu*mu;
        float rstd = rsqrtf(var + EPS);
        int c = h*DHH + tid;
        float hn = (v - mu) * rstd * gn[c];
        hn += sk[c] * g_cact[base + c];
        float z = g_up[(size_t)row * 2048 + II + c];
        hn *= z / (1.f + __expf(-z));
        g_h[base + c] = hn;
        __syncthreads();
    }
}

// ------------------------------- host -----------------------------------------
static inline void launch_gemm(const float* A, int lda, const float* B, int ldb,
                               float* C, int ldc, int M, int N, int K,
                               const float* bias, const float* res, int ldres)
{
    dim3 grid(N / 128, M / 128);
    sgemm_kernel<<<grid, 256>>>(A, lda, B, ldb, C, ldc, K, bias, res, ldres);
}

extern "C" void kernel_launch(void* const* d_in, const int* in_sizes, int n_in,
                              void* d_out, int out_size)
{
    (void)in_sizes; (void)n_in; (void)out_size;
    const float* x      = (const float*)d_in[0];
    const float* ln_g   = (const float*)d_in[1];
    const float* ln_b   = (const float*)d_in[2];
    const float* w_up   = (const float*)d_in[3];
    const float* conv_w = (const float*)d_in[4];
    const float* conv_b = (const float*)d_in[5];
    const float* wq     = (const float*)d_in[6];
    const float* wk     = (const float*)d_in[7];
    const float* wv     = (const float*)d_in[8];
    const float* w_i    = (const float*)d_in[9];
    const float* b_i    = (const float*)d_in[10];
    const float* w_f    = (const float*)d_in[11];
    const float* b_f    = (const float*)d_in[12];
    const float* skip   = (const float*)d_in[13];
    const float* gn_g   = (const float*)d_in[14];
    const float* w_down = (const float*)d_in[15];
    const float* b_down = (const float*)d_in[16];
    const float* w_fin  = (const float*)d_in[17];
    const float* b_fin  = (const float*)d_in[18];

    float *xn, *up, *cact, *q, *k, *v, *hb, *x1;
    cudaGetSymbolAddress((void**)&xn,   g_xn);
    cudaGetSymbolAddress((void**)&up,   g_up);
    cudaGetSymbolAddress((void**)&cact, g_cact);
    cudaGetSymbolAddress((void**)&q,    g_q);
    cudaGetSymbolAddress((void**)&k,    g_k);
    cudaGetSymbolAddress((void**)&v,    g_v);
    cudaGetSymbolAddress((void**)&hb,   g_h);
    cudaGetSymbolAddress((void**)&x1,   g_x1);

    cudaFuncSetAttribute(attn_kernel, cudaFuncAttributeMaxDynamicSharedMemorySize,
                         ATT_SMEM_FLOATS * (int)sizeof(float));

    const float* cur = x;
    for (int l = 0; l < 2; l++) {
        ln_kernel<<<BSR, 256>>>(cur, ln_g + l*EE, ln_b + l*EE, xn);
        // up: (8192,512)@(512,2048)
        launch_gemm(xn, EE, w_up + (size_t)l*EE*2048, 2048, up, 2048,
                    BSR, 2048, EE, nullptr, nullptr, 0);
        conv_silu_kernel<<<(BSR*II)/256, 256>>>(conv_w + l*KKC*II, conv_b + l*II);
        // q,k: c_act @ (1024,1024); v: x_m @ (1024,1024)
        launch_gemm(cact, II, wq + (size_t)l*II*II, II, q, II, BSR, II, II, nullptr, nullptr, 0);
        launch_gemm(cact, II, wk + (size_t)l*II*II, II, k, II, BSR, II, II, nullptr, nullptr, 0);
        launch_gemm(up, 2048, wv + (size_t)l*II*II, II, v, II, BSR, II, II, nullptr, nullptr, 0);
        gates_kernel<<<BSR, 256>>>(w_i + (size_t)l*3*II*HH, b_i + l*HH,
                                   w_f + (size_t)l*3*II*HH, b_f + l*HH);
        cumsum_kernel<<<BB*HH, SS>>>();
        attn_kernel<<<dim3(SS/32, BB*HH), 256, ATT_SMEM_FLOATS * sizeof(float)>>>();
        headgate_kernel<<<BSR, 256>>>(gn_g + l*II, skip + l*II);
        // down: (8192,1024)@(1024,512) + b_down + residual
        launch_gemm(hb, II, w_down + (size_t)l*II*EE, EE, x1, EE,
                    BSR, EE, II, b_down + l*EE, cur, EE);
        cur = x1;
    }
    // final: (8192,512)@(512,128) + b_fin
    launch_gemm(x1, EE, w_fin, 128, (float*)d_out, 128,
                BSR, 128, EE, b_fin, nullptr, 0);
}

// round 3
// speedup vs baseline: 2.1758x; 2.1758x over previous
#include <cuda_runtime.h>
#include <cstdint>
#include <math.h>

// Problem dims
#define BB   8
#define SS   1024
#define EE   512
#define II   1024
#define HH   4
#define DHH  256
#define KKC  4
#define BSR  (BB*SS)          // 8192 rows
#define EPS  1e-5f

// ---------------- scratch (static device memory; rewritten every call) ----------
__device__ float g_xn  [BSR*EE];
__device__ float g_up  [BSR*2048];        // x_m = cols [0,1024), z = cols [1024,2048)
__device__ float g_cact[BSR*II];
__device__ float g_q   [BSR*II];
__device__ float g_k   [BSR*II];
__device__ float g_v   [BSR*II];
__device__ float g_h   [BSR*II];
__device__ float g_x1  [BSR*EE];
__device__ float g_ipre[BB*HH*SS];
__device__ float g_fpre[BB*HH*SS];
__device__ float g_lfc [BB*HH*SS];
__device__ float g_wT  [9502720];         // transposed weights (38 MB)

// ================= tf32 mma.sync GEMM (sm_80+ path, valid on sm_103) ===========
// C[M,N] = A[M,K] @ W[K,N], BT = W^T ([N,K] row-major).
// CTA tile 128x128, BK=32, 256 thr = 8 warps (2m x 4n), warp tile 64x32.
// smem: per buffer A[128][32] f32 + B(nT)[128][32] f32, 16B-chunk xor swizzle.

__device__ __forceinline__ uint32_t f2tf32(float f) {
    uint32_t r;
    asm("cvt.rna.tf32.f32 %0, %1;" : "=r"(r) : "f"(f));
    return r;
}

__device__ __forceinline__ void ldg_tile(float4* pa, float4* pb,
                                         const float* A, int lda,
                                         const float* BT, int K,
                                         int row0, int col0, int k0, int tid)
{
    const float* Ag = A + (size_t)row0 * lda + k0;
    const float* Bg = BT + (size_t)col0 * K + k0;
    #pragma unroll
    for (int j = 0; j < 4; j++) {
        int i = tid + 256 * j;             // 1024 float4: 128 rows x 8 chunks
        int r = i >> 3, c = i & 7;
        pa[j] = *(const float4*)(Ag + (size_t)r * lda + (c << 2));
        pb[j] = *(const float4*)(Bg + (size_t)r * K   + (c << 2));
    }
}

__device__ __forceinline__ void sts_tile(char* bufA, char* bufB,
                                         const float4* pa, const float4* pb, int tid)
{
    #pragma unroll
    for (int j = 0; j < 4; j++) {
        int i = tid + 256 * j;
        int m = i >> 3, c = i & 7;
        uint32_t off = (uint32_t)(m << 7) + (uint32_t)((c ^ (m & 7)) << 4);
        uint4 va = make_uint4(f2tf32(pa[j].x), f2tf32(pa[j].y), f2tf32(pa[j].z), f2tf32(pa[j].w));
        uint4 vb = make_uint4(f2tf32(pb[j].x), f2tf32(pb[j].y), f2tf32(pb[j].z), f2tf32(pb[j].w));
        *(uint4*)(bufA + off) = va;
        *(uint4*)(bufB + off) = vb;
    }
}

__device__ __forceinline__ void compute_tile(const char* bufA, const char* bufB,
                                             float d[4][4][4],
                                             int warp_m, int warp_n,
                                             int laneR, int laneC)
{
    const char* aBase = bufA + (warp_m * 64 + laneR) * 128 + laneC * 4;
    const char* bBase = bufB + (warp_n * 32 + laneR) * 128 + laneC * 4;
    #pragma unroll
    for (int ks = 0; ks < 4; ks++) {
        uint32_t c0 = (uint32_t)(((2 * ks)     ^ laneR) << 4);
        uint32_t c1 = (uint32_t)(((2 * ks + 1) ^ laneR) << 4);
        uint32_t a[4][4], b[4][2];
        #pragma unroll
        for (int mf = 0; mf < 4; mf++) {
            const char* p = aBase + mf * (16 * 128);
            a[mf][0] = *(const uint32_t*)(p + c0);
            a[mf][1] = *(const uint32_t*)(p + 8 * 128 + c0);
            a[mf][2] = *(const uint32_t*)(p + c1);
            a[mf][3] = *(const uint32_t*)(p + 8 * 128 + c1);
        }
        #pragma unroll
        for (int nf = 0; nf < 4; nf++) {
            const char* p = bBase + nf * (8 * 128);
            b[nf][0] = *(const uint32_t*)(p + c0);
            b[nf][1] = *(const uint32_t*)(p + c1);
        }
        #pragma unroll
        for (int mf = 0; mf < 4; mf++)
            #pragma unroll
            for (int nf = 0; nf < 4; nf++)
                asm volatile(
                    "mma.sync.aligned.m16n8k8.row.col.f32.tf32.tf32.f32 "
                    "{%0,%1,%2,%3}, {%4,%5,%6,%7}, {%8,%9}, {%0,%1,%2,%3};"
                    : "+f"(d[mf][nf][0]), "+f"(d[mf][nf][1]),
                      "+f"(d[mf][nf][2]), "+f"(d[mf][nf][3])
                    : "r"(a[mf][0]), "r"(a[mf][1]), "r"(a[mf][2]), "r"(a[mf][3]),
                      "r"(b[nf][0]), "r"(b[nf][1]));
    }
}

#define GEMM_SMEM (4 * 16384)   // 2 buffers x (A 16KB + B 16KB)

__global__ __launch_bounds__(256) void tf32gemm_kernel(
    const float* __restrict__ A, int lda,
    const float* __restrict__ BT,           // [N,K] row-major, ldb = K
    float* __restrict__ C, int ldc, int K,
    const float* __restrict__ bias,
    const float* __restrict__ res, int ldres)
{
    extern __shared__ __align__(128) char sm[];
    char* bufA[2] = { sm,             sm + 32768 };
    char* bufB[2] = { sm + 16384,     sm + 49152 };

    int tid = threadIdx.x;
    int wid = tid >> 5, lane = tid & 31;
    int laneR = lane >> 2, laneC = lane & 3;
    int warp_m = wid & 1, warp_n = wid >> 1;
    int row0 = blockIdx.y * 128, col0 = blockIdx.x * 128;

    float d[4][4][4];
    #pragma unroll
    for (int i = 0; i < 4; i++)
        #pragma unroll
        for (int j = 0; j < 4; j++)
            #pragma unroll
            for (int u = 0; u < 4; u++) d[i][j][u] = 0.f;

    const int NK = K >> 5;
    float4 pa[4], pb[4];

    ldg_tile(pa, pb, A, lda, BT, K, row0, col0, 0, tid);
    sts_tile(bufA[0], bufB[0], pa, pb, tid);
    __syncthreads();

    #pragma unroll 1
    for (int kt = 0; kt < NK; kt++) {
        bool last = (kt == NK - 1);
        if (!last)
            ldg_tile(pa, pb, A, lda, BT, K, row0, col0, (kt + 1) << 5, tid);
        compute_tile(bufA[kt & 1], bufB[kt & 1], d, warp_m, warp_n, laneR, laneC);
        if (!last) {
            sts_tile(bufA[(kt + 1) & 1], bufB[(kt + 1) & 1], pa, pb, tid);
            __syncthreads();
        }
    }

    // Epilogue: float2 stores, fused bias + residual
    #pragma unroll
    for (int mf = 0; mf < 4; mf++) {
        int r = row0 + warp_m * 64 + mf * 16 + laneR;
        #pragma unroll
        for (int nf = 0; nf < 4; nf++) {
            int cc = col0 + warp_n * 32 + nf * 8 + 2 * laneC;
            float2 v0 = make_float2(d[mf][nf][0], d[mf][nf][1]);
            float2 v1 = make_float2(d[mf][nf][2], d[mf][nf][3]);
            if (bias) {
                float2 bv = *(const float2*)(bias + cc);
                v0.x += bv.x; v0.y += bv.y;
                v1.x += bv.x; v1.y += bv.y;
            }
            if (res) {
                float2 r0 = *(const float2*)(res + (size_t)r * ldres + cc);
                float2 r1 = *(const float2*)(res + (size_t)(r + 8) * ldres + cc);
                v0.x += r0.x; v0.y += r0.y;
                v1.x += r1.x; v1.y += r1.y;
            }
            *(float2*)(C + (size_t)r * ldc + cc)       = v0;
            *(float2*)(C + (size_t)(r + 8) * ldc + cc) = v1;
        }
    }
}

// ---------------- weight transpose: in[K,N] -> out[N,K] ------------------------
__global__ __launch_bounds__(256) void transpose_kernel(const float* __restrict__ in,
                                                        float* __restrict__ out,
                                                        int K, int N)
{
    __shared__ float t[32][33];
    int kb = blockIdx.y * 32, nb = blockIdx.x * 32;
    int tx = threadIdx.x & 31, ty = threadIdx.x >> 5;
    #pragma unroll
    for (int j = 0; j < 32; j += 8)
        t[ty + j][tx] = in[(size_t)(kb + ty + j) * N + nb + tx];
    __syncthreads();
    #pragma unroll
    for (int j = 0; j < 32; j += 8)
        out[(size_t)(nb + ty + j) * K + kb + tx] = t[tx][ty + j];
}

// ---------------- LayerNorm over E=512 ----------------
__global__ __launch_bounds__(256) void ln_kernel(const float* __restrict__ x,
                                                 const float* __restrict__ g,
                                                 const float* __restrict__ b,
                                                 float* __restrict__ y)
{
    int row = blockIdx.x;
    const float* xr = x + (size_t)row * EE;
    float s = 0.f, s2 = 0.f;
    for (int c = threadIdx.x; c < EE; c += 256) { float v = xr[c]; s += v; s2 += v*v; }
    __shared__ float sh[64];
    for (int o = 16; o; o >>= 1) {
        s  += __shfl_down_sync(0xffffffffu, s,  o);
        s2 += __shfl_down_sync(0xffffffffu, s2, o);
    }
    int wid = threadIdx.x >> 5, lane = threadIdx.x & 31;
    if (lane == 0) { sh[wid] = s; sh[32+wid] = s2; }
    __syncthreads();
    if (threadIdx.x == 0) {
        float ts = 0.f, ts2 = 0.f;
        for (int w = 0; w < 8; w++) { ts += sh[w]; ts2 += sh[32+w]; }
        sh[0] = ts; sh[32] = ts2;
    }
    __syncthreads();
    float mu  = sh[0]  * (1.f/EE);
    float var = sh[32] * (1.f/EE) - mu*mu;
    float rstd = rsqrtf(var + EPS);
    float* yr = y + (size_t)row * EE;
    for (int c = threadIdx.x; c < EE; c += 256)
        yr[c] = (xr[c] - mu) * rstd * g[c] + b[c];
}

// ---------------- causal depthwise conv (K=4) + SiLU -----------------
__global__ __launch_bounds__(256) void conv_silu_kernel(const float* __restrict__ cw,
                                                        const float* __restrict__ cb)
{
    int idx = blockIdx.x * 256 + threadIdx.x;
    int c   = idx & (II - 1);
    int row = idx >> 10;
    int t   = row & (SS - 1);
    float acc = cb[c];
    const float* base = g_up + (size_t)row * 2048 + c;
    #pragma unroll
    for (int j = 0; j < KKC; j++) {
        int tt = t - (KKC - 1) + j;
        if (tt >= 0) acc += base[(j - (KKC - 1)) * 2048] * cw[j * II + c];
    }
    g_cact[idx] = acc / (1.f + __expf(-acc));
}

// ---------------- gate projections: ipre/fpre[b,h,t] ---------------------------
__global__ __launch_bounds__(256) void gates_kernel(const float* __restrict__ wi,
                                                    const float* __restrict__ bi,
                                                    const float* __restrict__ wf,
                                                    const float* __restrict__ bf)
{
    int row = blockIdx.x;
    const float* q = g_q + (size_t)row * II;
    const float* k = g_k + (size_t)row * II;
    const float* v = g_v + (size_t)row * II;
    float ai[HH] = {0,0,0,0}, af[HH] = {0,0,0,0};
    for (int d = threadIdx.x; d < II; d += 256) {
        float qv = q[d], kv = k[d], vv = v[d];
        const float* wiq = wi + (size_t)d * HH;
        const float* wik = wi + (size_t)(II + d) * HH;
        const float* wiv = wi + (size_t)(2*II + d) * HH;
        const float* wfq = wf + (size_t)d * HH;
        const float* wfk = wf + (size_t)(II + d) * HH;
        const float* wfv = wf + (size_t)(2*II + d) * HH;
        #pragma unroll
        for (int h2 = 0; h2 < HH; h2++) {
            ai[h2] += qv*wiq[h2] + kv*wik[h2] + vv*wiv[h2];
            af[h2] += qv*wfq[h2] + kv*wfk[h2] + vv*wfv[h2];
        }
    }
    __shared__ float red[64];
    int lane = threadIdx.x & 31, wid = threadIdx.x >> 5;
    #pragma unroll
    for (int s = 0; s < 8; s++) {
        float x = (s < 4) ? ai[s] : af[s-4];
        for (int o = 16; o; o >>= 1) x += __shfl_down_sync(0xffffffffu, x, o);
        if (lane == 0) red[s * 8 + wid] = x;
    }
    __syncthreads();
    if (threadIdx.x < 64) {
        float x = red[threadIdx.x];
        x += __shfl_down_sync(0xffffffffu, x, 4, 8);
        x += __shfl_down_sync(0xffffffffu, x, 2, 8);
        x += __shfl_down_sync(0xffffffffu, x, 1, 8);
        if ((threadIdx.x & 7) == 0) {
            int s = threadIdx.x >> 3;
            int b = row >> 10, t = row & (SS - 1);
            if (s < 4) g_ipre[((size_t)b*HH + s)     * SS + t] = x + bi[s];
            else       g_fpre[((size_t)b*HH + (s-4)) * SS + t] = x + bf[s-4];
        }
    }
}

// ---------------- log-sigmoid + inclusive cumsum over S -----------------
__global__ __launch_bounds__(1024) void cumsum_kernel()
{
    int bh = blockIdx.x;
    int t  = threadIdx.x;
    float f  = g_fpre[bh * SS + t];
    float lf = (f > 0.f) ? -log1pf(__expf(-f)) : f - log1pf(__expf(f));
    __shared__ float sc[SS];
    sc[t] = lf;
    __syncthreads();
    for (int off = 1; off < SS; off <<= 1) {
        float v = (t >= off) ? sc[t - off] : 0.f;
        __syncthreads();
        sc[t] += v;
        __syncthreads();
    }
    g_lfc[bh * SS + t] = sc[t];
}

// ---------------- fused causal mLSTM attention (flash-style) -------------------
#define ATT_SMEM_FLOATS (32*256 + 32*257 + 32*256 + 32*33 + 64)
__global__ __launch_bounds__(256) void attn_kernel()
{
    extern __shared__ float smf[];
    float* q_sh  = smf;
    float* k_sh  = q_sh + 32*256;
    float* v_sh  = k_sh + 32*257;
    float* w_sh  = v_sh + 32*256;
    float* lfc_s = w_sh + 32*33;
    float* ipr_s = lfc_s + 32;

    int tb = blockIdx.x, bh = blockIdx.y;
    int b = bh >> 2, h = bh & 3;
    int tid = threadIdx.x;
    int ty = tid >> 3, tx = tid & 7;
    int t0 = tb * 32;
    size_t qkvbase = ((size_t)b * SS) * II + h * DHH;

    for (int r = 0; r < 32; r++)
        q_sh[r*256 + tid] = g_q[qkvbase + (size_t)(t0 + r) * II + tid] * 0.0625f;

    int t_glob = t0 + ty;
    float lfc_t = g_lfc[bh * SS + t_glob];
    float m = -1e30f, ssum = 0.f;
    float acc[32];
    #pragma unroll
    for (int j = 0; j < 32; j++) acc[j] = 0.f;

    for (int sb = 0; sb <= tb; sb++) {
        int s0 = sb * 32;
        __syncthreads();
        for (int r = 0; r < 32; r++) {
            k_sh[r*257 + tid] = g_k[qkvbase + (size_t)(s0 + r) * II + tid];
            v_sh[r*256 + tid] = g_v[qkvbase + (size_t)(s0 + r) * II + tid];
        }
        if (tid < 32) {
            lfc_s[tid] = g_lfc [bh * SS + s0 + tid];
            ipr_s[tid] = g_ipre[bh * SS + s0 + tid];
        }
        __syncthreads();

        float dot0=0.f, dot1=0.f, dot2=0.f, dot3=0.f;
        const float* qr  = q_sh + ty*256;
        const float* k0p = k_sh + tx*257;
        #pragma unroll 8
        for (int d = 0; d < 256; d++) {
            float qv = qr[d];
            dot0 = fmaf(qv, k0p[d],          dot0);
            dot1 = fmaf(qv, k0p[ 8*257 + d], dot1);
            dot2 = fmaf(qv, k0p[16*257 + d], dot2);
            dot3 = fmaf(qv, k0p[24*257 + d], dot3);
        }
        float dots[4] = {dot0, dot1, dot2, dot3};
        float logd[4];
        float mb = -1e30f;
        #pragma unroll
        for (int u = 0; u < 4; u++) {
            int sl = tx + 8*u;
            bool valid = (s0 + sl) <= t_glob;
            float ld = valid ? (lfc_t - lfc_s[sl] + ipr_s[sl]) : -1e30f;
            logd[u] = ld;
            mb = fmaxf(mb, ld);
        }
        mb = fmaxf(mb, __shfl_xor_sync(0xffffffffu, mb, 1));
        mb = fmaxf(mb, __shfl_xor_sync(0xffffffffu, mb, 2));
        mb = fmaxf(mb, __shfl_xor_sync(0xffffffffu, mb, 4));
        float m_new = fmaxf(m, mb);
        float scale = __expf(m - m_new);
        float wsum = 0.f;
        #pragma unroll
        for (int u = 0; u < 4; u++) {
            float wv = __expf(logd[u] - m_new) * dots[u];
            w_sh[ty*33 + tx + 8*u] = wv;
            wsum += wv;
        }
        ssum = ssum * scale + wsum;
        m = m_new;
        __syncthreads();

        #pragma unroll
        for (int j = 0; j < 32; j++) acc[j] *= scale;
        for (int sl = 0; sl < 32; sl++) {
            float wv = w_sh[ty*33 + sl];
            const float* vr = v_sh + sl*256 + tx;
            #pragma unroll
            for (int j = 0; j < 32; j++)
                acc[j] = fmaf(wv, vr[8*j], acc[j]);
        }
    }
    ssum += __shfl_xor_sync(0xffffffffu, ssum, 1);
    ssum += __shfl_xor_sync(0xffffffffu, ssum, 2);
    ssum += __shfl_xor_sync(0xffffffffu, ssum, 4);
    float n   = fmaxf(fabsf(ssum), __expf(-m));
    float inv = 1.f / n;
    float* outp = g_h + qkvbase + (size_t)t_glob * II + tx;
    #pragma unroll
    for (int j = 0; j < 32; j++) outp[8*j] = acc[j] * inv;
}

// ---------------- per-head norm + gn_g + skip*c_act + *silu(z) -------------
__global__ __launch_bounds__(256) void headgate_kernel(const float* __restrict__ gn,
                                                       const float* __restrict__ sk)
{
    int row = blockIdx.x;
    int tid = threadIdx.x;
    __shared__ float sh[16];
    __shared__ float stat[2];
    size_t base = (size_t)row * II;
    for (int h = 0; h < HH; h++) {
        float v = g_h[base + h*DHH + tid];
        float s = v, s2 = v*v;
        for (int o = 16; o; o >>= 1) {
            s  += __shfl_down_sync(0xffffffffu, s,  o);
            s2 += __shfl_down_sync(0xffffffffu, s2, o);
        }
        int wid = tid >> 5, lane = tid & 31;
        if (lane == 0) { sh[wid] = s; sh[8+wid] = s2; }
        __syncthreads();
        if (tid == 0) {
            float ts = 0.f, ts2 = 0.f;
            for (int w = 0; w < 8; w++) { ts += sh[w]; ts2 += sh[8+w]; }
            stat[0] = ts * (1.f/DHH); stat[1] = ts2 * (1.f/DHH);
        }
        __syncthreads();
        float mu = stat[0];
        float var = stat[1] - mu*mu;
        float rstd = rsqrtf(var + EPS);
        int c = h*DHH + tid;
        float hn = (v - mu) * rstd * gn[c];
        hn += sk[c] * g_cact[base + c];
        float z = g_up[(size_t)row * 2048 + II + c];
        hn *= z / (1.f + __expf(-z));
        g_h[base + c] = hn;
        __syncthreads();
    }
}

// ------------------------------- host -----------------------------------------
#define WT_PER   4718592
#define WT_UP(l)   (g_wT_ptr + (size_t)(l)*WT_PER)
#define WT_Q(l)    (g_wT_ptr + (size_t)(l)*WT_PER + 1048576)
#define WT_K(l)    (g_wT_ptr + (size_t)(l)*WT_PER + 2097152)
#define WT_V(l)    (g_wT_ptr + (size_t)(l)*WT_PER + 3145728)
#define WT_DOWN(l) (g_wT_ptr + (size_t)(l)*WT_PER + 4194304)
#define WT_FIN     (g_wT_ptr + (size_t)2*WT_PER)

static inline void launch_gemm(const float* A, int lda, const float* BT,
                               float* C, int ldc, int M, int N, int K,
                               const float* bias, const float* res, int ldres)
{
    dim3 grid(N / 128, M / 128);
    tf32gemm_kernel<<<grid, 256, GEMM_SMEM>>>(A, lda, BT, C, ldc, K, bias, res, ldres);
}

extern "C" void kernel_launch(void* const* d_in, const int* in_sizes, int n_in,
                              void* d_out, int out_size)
{
    (void)in_sizes; (void)n_in; (void)out_size;
    const float* x      = (const float*)d_in[0];
    const float* ln_g   = (const float*)d_in[1];
    const float* ln_b   = (const float*)d_in[2];
    const float* w_up   = (const float*)d_in[3];
    const float* conv_w = (const float*)d_in[4];
    const float* conv_b = (const float*)d_in[5];
    const float* wq     = (const float*)d_in[6];
    const float* wk     = (const float*)d_in[7];
    const float* wv     = (const float*)d_in[8];
    const float* w_i    = (const float*)d_in[9];
    const float* b_i    = (const float*)d_in[10];
    const float* w_f    = (const float*)d_in[11];
    const float* b_f    = (const float*)d_in[12];
    const float* skip   = (const float*)d_in[13];
    const float* gn_g   = (const float*)d_in[14];
    const float* w_down = (const float*)d_in[15];
    const float* b_down = (const float*)d_in[16];
    const float* w_fin  = (const float*)d_in[17];
    const float* b_fin  = (const float*)d_in[18];

    float *xn, *up, *cact, *q, *k, *v, *hb, *x1, *g_wT_ptr;
    cudaGetSymbolAddress((void**)&xn,   g_xn);
    cudaGetSymbolAddress((void**)&up,   g_up);
    cudaGetSymbolAddress((void**)&cact, g_cact);
    cudaGetSymbolAddress((void**)&q,    g_q);
    cudaGetSymbolAddress((void**)&k,    g_k);
    cudaGetSymbolAddress((void**)&v,    g_v);
    cudaGetSymbolAddress((void**)&hb,   g_h);
    cudaGetSymbolAddress((void**)&x1,   g_x1);
    cudaGetSymbolAddress((void**)&g_wT_ptr, g_wT);

    cudaFuncSetAttribute(attn_kernel, cudaFuncAttributeMaxDynamicSharedMemorySize,
                         ATT_SMEM_FLOATS * (int)sizeof(float));
    cudaFuncSetAttribute(tf32gemm_kernel, cudaFuncAttributeMaxDynamicSharedMemorySize,
                         GEMM_SMEM);

    // ---- transpose all weights (per-call; deterministic) ----
    for (int l = 0; l < 2; l++) {
        transpose_kernel<<<dim3(2048/32, 512/32), 256>>>(w_up  + (size_t)l*512*2048, WT_UP(l),   512, 2048);
        transpose_kernel<<<dim3(1024/32,1024/32), 256>>>(wq    + (size_t)l*II*II,    WT_Q(l),    1024, 1024);
        transpose_kernel<<<dim3(1024/32,1024/32), 256>>>(wk    + (size_t)l*II*II,    WT_K(l),    1024, 1024);
        transpose_kernel<<<dim3(1024/32,1024/32), 256>>>(wv    + (size_t)l*II*II,    WT_V(l),    1024, 1024);
        transpose_kernel<<<dim3( 512/32,1024/32), 256>>>(w_down+ (size_t)l*II*EE,    WT_DOWN(l), 1024, 512);
    }
    transpose_kernel<<<dim3(128/32, 512/32), 256>>>(w_fin, WT_FIN, 512, 128);

    const float* cur = x;
    for (int l = 0; l < 2; l++) {
        ln_kernel<<<BSR, 256>>>(cur, ln_g + l*EE, ln_b + l*EE, xn);
        launch_gemm(xn, EE, WT_UP(l), up, 2048, BSR, 2048, EE, nullptr, nullptr, 0);
        conv_silu_kernel<<<(BSR*II)/256, 256>>>(conv_w + l*KKC*II, conv_b + l*II);
        launch_gemm(cact, II,   WT_Q(l), q, II, BSR, II, II, nullptr, nullptr, 0);
        launch_gemm(cact, II,   WT_K(l), k, II, BSR, II, II, nullptr, nullptr, 0);
        launch_gemm(up,   2048, WT_V(l), v, II, BSR, II, II, nullptr, nullptr, 0);
        gates_kernel<<<BSR, 256>>>(w_i + (size_t)l*3*II*HH, b_i + l*HH,
                                   w_f + (size_t)l*3*II*HH, b_f + l*HH);
        cumsum_kernel<<<BB*HH, SS>>>();
        attn_kernel<<<dim3(SS/32, BB*HH), 256, ATT_SMEM_FLOATS * sizeof(float)>>>();
        headgate_kernel<<<BSR, 256>>>(gn_g + l*II, skip + l*II);
        launch_gemm(hb, II, WT_DOWN(l), x1, EE, BSR, EE, II, b_down + l*EE, cur, EE);
        cur = x1;
    }
    // final: (8192,512)@(512,128) + b_fin
    launch_gemm(x1, EE, WT_FIN, (float*)d_out, 128, BSR, 128, EE, b_fin, nullptr, 0);
}

// round 4
// speedup vs baseline: 3.9922x; 1.8348x over previous
#include <cuda_runtime.h>
#include <cstdint>
#include <math.h>

// Problem dims
#define BB   8
#define SS   1024
#define EE   512
#define II   1024
#define HH   4
#define DHH  256
#define KKC  4
#define BSR  (BB*SS)          // 8192 rows
#define EPS  1e-5f

// ---------------- scratch (static device memory; rewritten every call) ----------
__device__ float g_xn  [BSR*EE];
__device__ float g_up  [BSR*2048];        // x_m = cols [0,1024), z = cols [1024,2048)
__device__ float g_cact[BSR*II];
__device__ float g_q   [BSR*II];
__device__ float g_k   [BSR*II];
__device__ float g_v   [BSR*II];
__device__ float g_h   [BSR*II];
__device__ float g_x1  [BSR*EE];
__device__ float g_ipre[BB*HH*SS];
__device__ float g_fpre[BB*HH*SS];
__device__ float g_u   [BB*HH*SS];        // ipre - lfc
__device__ float g_mx  [BB*HH*SS];        // prefix max of u
__device__ float g_mm  [BB*HH*SS];        // m_t = lfc + M
__device__ float g_vT  [32*256*1024];     // V^T per (b,h): [bh][d][t], tf32-packed (32MB)
__device__ float g_wT  [9502720];         // transposed weights (38 MB)

__device__ __forceinline__ uint32_t f2tf32(float f) {
    uint32_t r;
    asm("cvt.rna.tf32.f32 %0, %1;" : "=r"(r) : "f"(f));
    return r;
}

__device__ __forceinline__ void mma_tf32(float* d, const uint32_t* a, uint32_t b0, uint32_t b1) {
    asm volatile("mma.sync.aligned.m16n8k8.row.col.f32.tf32.tf32.f32 "
        "{%0,%1,%2,%3}, {%4,%5,%6,%7}, {%8,%9}, {%0,%1,%2,%3};"
        : "+f"(d[0]), "+f"(d[1]), "+f"(d[2]), "+f"(d[3])
        : "r"(a[0]), "r"(a[1]), "r"(a[2]), "r"(a[3]), "r"(b0), "r"(b1));
}

// ================= tf32 mma.sync GEMM (unchanged from R3, passing) =============
__device__ __forceinline__ void ldg_tile(float4* pa, float4* pb,
                                         const float* A, int lda,
                                         const float* BT, int K,
                                         int row0, int col0, int k0, int tid)
{
    const float* Ag = A + (size_t)row0 * lda + k0;
    const float* Bg = BT + (size_t)col0 * K + k0;
    #pragma unroll
    for (int j = 0; j < 4; j++) {
        int i = tid + 256 * j;
        int r = i >> 3, c = i & 7;
        pa[j] = *(const float4*)(Ag + (size_t)r * lda + (c << 2));
        pb[j] = *(const float4*)(Bg + (size_t)r * K   + (c << 2));
    }
}

__device__ __forceinline__ void sts_tile(char* bufA, char* bufB,
                                         const float4* pa, const float4* pb, int tid)
{
    #pragma unroll
    for (int j = 0; j < 4; j++) {
        int i = tid + 256 * j;
        int m = i >> 3, c = i & 7;
        uint32_t off = (uint32_t)(m << 7) + (uint32_t)((c ^ (m & 7)) << 4);
        uint4 va = make_uint4(f2tf32(pa[j].x), f2tf32(pa[j].y), f2tf32(pa[j].z), f2tf32(pa[j].w));
        uint4 vb = make_uint4(f2tf32(pb[j].x), f2tf32(pb[j].y), f2tf32(pb[j].z), f2tf32(pb[j].w));
        *(uint4*)(bufA + off) = va;
        *(uint4*)(bufB + off) = vb;
    }
}

__device__ __forceinline__ void compute_tile(const char* bufA, const char* bufB,
                                             float d[4][4][4],
                                             int warp_m, int warp_n,
                                             int laneR, int laneC)
{
    const char* aBase = bufA + (warp_m * 64 + laneR) * 128 + laneC * 4;
    const char* bBase = bufB + (warp_n * 32 + laneR) * 128 + laneC * 4;
    #pragma unroll
    for (int ks = 0; ks < 4; ks++) {
        uint32_t c0 = (uint32_t)(((2 * ks)     ^ laneR) << 4);
        uint32_t c1 = (uint32_t)(((2 * ks + 1) ^ laneR) << 4);
        uint32_t a[4][4], b[4][2];
        #pragma unroll
        for (int mf = 0; mf < 4; mf++) {
            const char* p = aBase + mf * (16 * 128);
            a[mf][0] = *(const uint32_t*)(p + c0);
            a[mf][1] = *(const uint32_t*)(p + 8 * 128 + c0);
            a[mf][2] = *(const uint32_t*)(p + c1);
            a[mf][3] = *(const uint32_t*)(p + 8 * 128 + c1);
        }
        #pragma unroll
        for (int nf = 0; nf < 4; nf++) {
            const char* p = bBase + nf * (8 * 128);
            b[nf][0] = *(const uint32_t*)(p + c0);
            b[nf][1] = *(const uint32_t*)(p + c1);
        }
        #pragma unroll
        for (int mf = 0; mf < 4; mf++)
            #pragma unroll
            for (int nf = 0; nf < 4; nf++)
                mma_tf32(d[mf][nf], a[mf], b[nf][0], b[nf][1]);
    }
}

#define GEMM_SMEM (4 * 16384)

__global__ __launch_bounds__(256) void tf32gemm_kernel(
    const float* __restrict__ A, int lda,
    const float* __restrict__ BT,
    float* __restrict__ C, int ldc, int K,
    const float* __restrict__ bias,
    const float* __restrict__ res, int ldres)
{
    extern __shared__ __align__(128) char sm[];
    char* bufA[2] = { sm,         sm + 32768 };
    char* bufB[2] = { sm + 16384, sm + 49152 };

    int tid = threadIdx.x;
    int wid = tid >> 5, lane = tid & 31;
    int laneR = lane >> 2, laneC = lane & 3;
    int warp_m = wid & 1, warp_n = wid >> 1;
    int row0 = blockIdx.y * 128, col0 = blockIdx.x * 128;

    float d[4][4][4];
    #pragma unroll
    for (int i = 0; i < 4; i++)
        #pragma unroll
        for (int j = 0; j < 4; j++)
            #pragma unroll
            for (int u = 0; u < 4; u++) d[i][j][u] = 0.f;

    const int NK = K >> 5;
    float4 pa[4], pb[4];

    ldg_tile(pa, pb, A, lda, BT, K, row0, col0, 0, tid);
    sts_tile(bufA[0], bufB[0], pa, pb, tid);
    __syncthreads();

    #pragma unroll 1
    for (int kt = 0; kt < NK; kt++) {
        bool last = (kt == NK - 1);
        if (!last)
            ldg_tile(pa, pb, A, lda, BT, K, row0, col0, (kt + 1) << 5, tid);
        compute_tile(bufA[kt & 1], bufB[kt & 1], d, warp_m, warp_n, laneR, laneC);
        if (!last) {
            sts_tile(bufA[(kt + 1) & 1], bufB[(kt + 1) & 1], pa, pb, tid);
            __syncthreads();
        }
    }

    #pragma unroll
    for (int mf = 0; mf < 4; mf++) {
        int r = row0 + warp_m * 64 + mf * 16 + laneR;
        #pragma unroll
        for (int nf = 0; nf < 4; nf++) {
            int cc = col0 + warp_n * 32 + nf * 8 + 2 * laneC;
            float2 v0 = make_float2(d[mf][nf][0], d[mf][nf][1]);
            float2 v1 = make_float2(d[mf][nf][2], d[mf][nf][3]);
            if (bias) {
                float2 bv = *(const float2*)(bias + cc);
                v0.x += bv.x; v0.y += bv.y;
                v1.x += bv.x; v1.y += bv.y;
            }
            if (res) {
                float2 r0 = *(const float2*)(res + (size_t)r * ldres + cc);
                float2 r1 = *(const float2*)(res + (size_t)(r + 8) * ldres + cc);
                v0.x += r0.x; v0.y += r0.y;
                v1.x += r1.x; v1.y += r1.y;
            }
            *(float2*)(C + (size_t)r * ldc + cc)       = v0;
            *(float2*)(C + (size_t)(r + 8) * ldc + cc) = v1;
        }
    }
}

// ---------------- weight transpose: in[K,N] -> out[N,K] ------------------------
__global__ __launch_bounds__(256) void transpose_kernel(const float* __restrict__ in,
                                                        float* __restrict__ out,
                                                        int K, int N)
{
    __shared__ float t[32][33];
    int kb = blockIdx.y * 32, nb = blockIdx.x * 32;
    int tx = threadIdx.x & 31, ty = threadIdx.x >> 5;
    #pragma unroll
    for (int j = 0; j < 32; j += 8)
        t[ty + j][tx] = in[(size_t)(kb + ty + j) * N + nb + tx];
    __syncthreads();
    #pragma unroll
    for (int j = 0; j < 32; j += 8)
        out[(size_t)(nb + ty + j) * K + kb + tx] = t[tx][ty + j];
}

// ---------------- V transpose per (b,h): g_v -> g_vT[bh][d][t], tf32-packed ----
__global__ __launch_bounds__(256) void vtrans_kernel(float* __restrict__ vT)
{
    __shared__ float t[32][33];
    int bh = blockIdx.z;
    int b = bh >> 2, h = bh & 3;
    int t0 = blockIdx.x * 32, d0 = blockIdx.y * 32;
    int tx = threadIdx.x & 31, ty = threadIdx.x >> 5;
    #pragma unroll
    for (int j = 0; j < 32; j += 8)
        t[ty + j][tx] = g_v[(size_t)(b * SS + t0 + ty + j) * II + h * DHH + d0 + tx];
    __syncthreads();
    #pragma unroll
    for (int j = 0; j < 32; j += 8)
        vT[((size_t)bh * DHH + d0 + ty + j) * SS + t0 + tx] =
            __uint_as_float(f2tf32(t[tx][ty + j]));
}

// ---------------- LayerNorm over E=512 ----------------
__global__ __launch_bounds__(256) void ln_kernel(const float* __restrict__ x,
                                                 const float* __restrict__ g,
                                                 const float* __restrict__ b,
                                                 float* __restrict__ y)
{
    int row = blockIdx.x;
    const float* xr = x + (size_t)row * EE;
    float s = 0.f, s2 = 0.f;
    for (int c = threadIdx.x; c < EE; c += 256) { float v = xr[c]; s += v; s2 += v*v; }
    __shared__ float sh[64];
    for (int o = 16; o; o >>= 1) {
        s  += __shfl_down_sync(0xffffffffu, s,  o);
        s2 += __shfl_down_sync(0xffffffffu, s2, o);
    }
    int wid = threadIdx.x >> 5, lane = threadIdx.x & 31;
    if (lane == 0) { sh[wid] = s; sh[32+wid] = s2; }
    __syncthreads();
    if (threadIdx.x == 0) {
        float ts = 0.f, ts2 = 0.f;
        for (int w = 0; w < 8; w++) { ts += sh[w]; ts2 += sh[32+w]; }
        sh[0] = ts; sh[32] = ts2;
    }
    __syncthreads();
    float mu  = sh[0]  * (1.f/EE);
    float var = sh[32] * (1.f/EE) - mu*mu;
    float rstd = rsqrtf(var + EPS);
    float* yr = y + (size_t)row * EE;
    for (int c = threadIdx.x; c < EE; c += 256)
        yr[c] = (xr[c] - mu) * rstd * g[c] + b[c];
}

// ---------------- causal depthwise conv (K=4) + SiLU -----------------
__global__ __launch_bounds__(256) void conv_silu_kernel(const float* __restrict__ cw,
                                                        const float* __restrict__ cb)
{
    int idx = blockIdx.x * 256 + threadIdx.x;
    int c   = idx & (II - 1);
    int row = idx >> 10;
    int t   = row & (SS - 1);
    float acc = cb[c];
    const float* base = g_up + (size_t)row * 2048 + c;
    #pragma unroll
    for (int j = 0; j < KKC; j++) {
        int tt = t - (KKC - 1) + j;
        if (tt >= 0) acc += base[(j - (KKC - 1)) * 2048] * cw[j * II + c];
    }
    g_cact[idx] = acc / (1.f + __expf(-acc));
}

// ---------------- gate projections: ipre/fpre[b,h,t] ---------------------------
__global__ __launch_bounds__(256) void gates_kernel(const float* __restrict__ wi,
                                                    const float* __restrict__ bi,
                                                    const float* __restrict__ wf,
                                                    const float* __restrict__ bf)
{
    int row = blockIdx.x;
    const float* q = g_q + (size_t)row * II;
    const float* k = g_k + (size_t)row * II;
    const float* v = g_v + (size_t)row * II;
    float ai[HH] = {0,0,0,0}, af[HH] = {0,0,0,0};
    for (int d = threadIdx.x; d < II; d += 256) {
        float qv = q[d], kv = k[d], vv = v[d];
        const float* wiq = wi + (size_t)d * HH;
        const float* wik = wi + (size_t)(II + d) * HH;
        const float* wiv = wi + (size_t)(2*II + d) * HH;
        const float* wfq = wf + (size_t)d * HH;
        const float* wfk = wf + (size_t)(II + d) * HH;
        const float* wfv = wf + (size_t)(2*II + d) * HH;
        #pragma unroll
        for (int h2 = 0; h2 < HH; h2++) {
            ai[h2] += qv*wiq[h2] + kv*wik[h2] + vv*wiv[h2];
            af[h2] += qv*wfq[h2] + kv*wfk[h2] + vv*wfv[h2];
        }
    }
    __shared__ float red[64];
    int lane = threadIdx.x & 31, wid = threadIdx.x >> 5;
    #pragma unroll
    for (int s = 0; s < 8; s++) {
        float x = (s < 4) ? ai[s] : af[s-4];
        for (int o = 16; o; o >>= 1) x += __shfl_down_sync(0xffffffffu, x, o);
        if (lane == 0) red[s * 8 + wid] = x;
    }
    __syncthreads();
    if (threadIdx.x < 64) {
        float x = red[threadIdx.x];
        x += __shfl_down_sync(0xffffffffu, x, 4, 8);
        x += __shfl_down_sync(0xffffffffu, x, 2, 8);
        x += __shfl_down_sync(0xffffffffu, x, 1, 8);
        if ((threadIdx.x & 7) == 0) {
            int s = threadIdx.x >> 3;
            int b = row >> 10, t = row & (SS - 1);
            if (s < 4) g_ipre[((size_t)b*HH + s)     * SS + t] = x + bi[s];
            else       g_fpre[((size_t)b*HH + (s-4)) * SS + t] = x + bf[s-4];
        }
    }
}

// ---------------- gate scan: lfc, u = ipre - lfc, M = runmax u, m = lfc + M -----
__global__ __launch_bounds__(1024) void cumsum_kernel()
{
    int bh = blockIdx.x;
    int t  = threadIdx.x;
    float f  = g_fpre[bh * SS + t];
    float lf = (f > 0.f) ? -log1pf(__expf(-f)) : f - log1pf(__expf(f));
    __shared__ float sc[SS];
    sc[t] = lf;
    __syncthreads();
    for (int off = 1; off < SS; off <<= 1) {
        float v = (t >= off) ? sc[t - off] : 0.f;
        __syncthreads();
        sc[t] += v;
        __syncthreads();
    }
    float lfc = sc[t];
    float u = g_ipre[bh * SS + t] - lfc;
    g_u[bh * SS + t] = u;
    __syncthreads();
    sc[t] = u;
    __syncthreads();
    for (int off = 1; off < SS; off <<= 1) {
        float v = (t >= off) ? sc[t - off] : -1e30f;
        __syncthreads();
        sc[t] = fmaxf(sc[t], v);
        __syncthreads();
    }
    float M = sc[t];
    g_mx[bh * SS + t] = M;
    g_mm[bh * SS + t] = lfc + M;
}

// ---------------- tensor-core causal mLSTM attention ---------------------------
// grid (bh=32, 16 t-tiles reversed). 256 thr, 8 warps (2m x 4n).
// GEMM1: S[64x64] = Qs[64x256] Ks^T  (warp tile 32x16)
// GEMM2: O[64x256] += P[64x64] VsT   (warp tile 32x64)
#define ATT2_SMEM 214272
__global__ __launch_bounds__(256) void attn2_kernel(const float* __restrict__ vT)
{
    extern __shared__ __align__(128) char sm2[];
    char*  Qs    = sm2;                       // [64][256] tf32, 1024B rows, 65536
    char*  Ks    = sm2 + 65536;               // [64][256] tf32
    char*  Vs    = sm2 + 131072;              // [256][64] tf32, 256B rows
    char*  Ps    = sm2 + 196608;              // [64][64] tf32, 256B rows, 16384
    float* u_sh  = (float*)(sm2 + 212992);    // [64]
    float* ss_sh = (float*)(sm2 + 213248);    // [4][64]

    int bh = blockIdx.x;
    int tb = (int)gridDim.y - 1 - (int)blockIdx.y;   // heavy tiles first
    int b = bh >> 2, h = bh & 3;
    int tid = threadIdx.x;
    int wid = tid >> 5, lane = tid & 31;
    int laneR = lane >> 2, laneC = lane & 3;
    int warp_m = wid & 1, warp_n = wid >> 1;
    int t0 = tb * 64;
    size_t qkvbase = ((size_t)b * SS) * II + (size_t)h * DHH;
    const float* vTb = vT + (size_t)bh * DHH * SS;

    // Q tile (scaled by DH^-0.5 = 1/16), tf32, swizzled
    #pragma unroll
    for (int j = 0; j < 16; j++) {
        int i = tid + 256 * j;
        int r = i >> 6, c = i & 63;
        float4 v = *(const float4*)(g_q + qkvbase + (size_t)(t0 + r) * II + (c << 2));
        uint4 w = make_uint4(f2tf32(v.x * 0.0625f), f2tf32(v.y * 0.0625f),
                             f2tf32(v.z * 0.0625f), f2tf32(v.w * 0.0625f));
        *(uint4*)(Qs + r * 1024 + ((c ^ (r & 7)) << 4)) = w;
    }

    float Mr[4], ssum[4];
    #pragma unroll
    for (int k = 0; k < 4; k++) {
        int row = warp_m * 32 + (k >> 1) * 16 + (k & 1) * 8 + laneR;
        Mr[k] = g_mx[bh * SS + t0 + row];
        ssum[k] = 0.f;
    }

    float o[2][8][4];
    #pragma unroll
    for (int mf = 0; mf < 2; mf++)
        #pragma unroll
        for (int nf = 0; nf < 8; nf++)
            #pragma unroll
            for (int u = 0; u < 4; u++) o[mf][nf][u] = 0.f;

    #pragma unroll 1
    for (int sb = 0; sb <= tb; sb++) {
        int s0 = sb * 64;
        __syncthreads();
        #pragma unroll
        for (int j = 0; j < 16; j++) {
            int i = tid + 256 * j;
            int r = i >> 6, c = i & 63;
            float4 v = *(const float4*)(g_k + qkvbase + (size_t)(s0 + r) * II + (c << 2));
            uint4 w = make_uint4(f2tf32(v.x), f2tf32(v.y), f2tf32(v.z), f2tf32(v.w));
            *(uint4*)(Ks + r * 1024 + ((c ^ (r & 7)) << 4)) = w;
        }
        #pragma unroll
        for (int j = 0; j < 16; j++) {
            int i = tid + 256 * j;
            int r = i >> 4, c = i & 15;
            float4 v = *(const float4*)(vTb + (size_t)r * SS + s0 + (c << 2));
            *(float4*)(Vs + (r << 8) + ((c ^ (r & 7)) << 4)) = v;  // already tf32 bits
        }
        if (tid < 64) u_sh[tid] = g_u[bh * SS + s0 + tid];
        __syncthreads();

        // ---- GEMM1: S = Q K^T (K-dim 256 = 32 k8 steps) ----
        float s8[2][2][4];
        #pragma unroll
        for (int mf = 0; mf < 2; mf++)
            #pragma unroll
            for (int nf = 0; nf < 2; nf++)
                #pragma unroll
                for (int u = 0; u < 4; u++) s8[mf][nf][u] = 0.f;
        {
            const char* aB = Qs + (warp_m * 32 + laneR) * 1024 + laneC * 4;
            const char* bB = Ks + (warp_n * 16 + laneR) * 1024 + laneC * 4;
            #pragma unroll
            for (int ks = 0; ks < 32; ks++) {
                uint32_t c0 = (uint32_t)(((2 * ks)     ^ laneR) << 4);
                uint32_t c1 = (uint32_t)(((2 * ks + 1) ^ laneR) << 4);
                uint32_t a[2][4], bf[2][2];
                #pragma unroll
                for (int mf = 0; mf < 2; mf++) {
                    const char* p = aB + mf * 16384;
                    a[mf][0] = *(const uint32_t*)(p + c0);
                    a[mf][1] = *(const uint32_t*)(p + 8192 + c0);
                    a[mf][2] = *(const uint32_t*)(p + c1);
                    a[mf][3] = *(const uint32_t*)(p + 8192 + c1);
                }
                #pragma unroll
                for (int nf = 0; nf < 2; nf++) {
                    const char* p = bB + nf * 8192;
                    bf[nf][0] = *(const uint32_t*)(p + c0);
                    bf[nf][1] = *(const uint32_t*)(p + c1);
                }
                #pragma unroll
                for (int mf = 0; mf < 2; mf++)
                    #pragma unroll
                    for (int nf = 0; nf < 2; nf++)
                        mma_tf32(s8[mf][nf], a[mf], bf[nf][0], bf[nf][1]);
            }
        }

        // ---- weights + mask + P (tf32) + running score sums ----
        bool diag = (sb == tb);
        #pragma unroll
        for (int mf = 0; mf < 2; mf++) {
            #pragma unroll
            for (int e = 0; e < 2; e++) {
                int row = warp_m * 32 + mf * 16 + e * 8 + laneR;
                int tg = t0 + row;
                float M = Mr[mf * 2 + e];
                #pragma unroll
                for (int nf = 0; nf < 2; nf++) {
                    int cb = warp_n * 16 + nf * 8 + 2 * laneC;
                    float d0 = s8[mf][nf][2 * e], d1 = s8[mf][nf][2 * e + 1];
                    float w0 = (!diag || (s0 + cb)     <= tg) ? __expf(u_sh[cb]     - M) : 0.f;
                    float w1 = (!diag || (s0 + cb + 1) <= tg) ? __expf(u_sh[cb + 1] - M) : 0.f;
                    uint2 pk = make_uint2(f2tf32(d0 * w0), f2tf32(d1 * w1));
                    ssum[mf * 2 + e] += __uint_as_float(pk.x) + __uint_as_float(pk.y);
                    *(uint2*)(Ps + (row << 8) + (((cb >> 2) ^ (row & 7)) << 4)
                              + ((cb & 3) << 2)) = pk;
                }
            }
        }
        __syncthreads();

        // ---- GEMM2: O += P V^T (K-dim 64 = 8 k8 steps) ----
        {
            const char* aB = Ps + (warp_m * 32 + laneR) * 256 + laneC * 4;
            const char* bB = Vs + (warp_n * 64 + laneR) * 256 + laneC * 4;
            #pragma unroll
            for (int ks = 0; ks < 8; ks++) {
                uint32_t c0 = (uint32_t)(((2 * ks)     ^ laneR) << 4);
                uint32_t c1 = (uint32_t)(((2 * ks + 1) ^ laneR) << 4);
                uint32_t a[2][4];
                #pragma unroll
                for (int mf = 0; mf < 2; mf++) {
                    const char* p = aB + mf * 4096;
                    a[mf][0] = *(const uint32_t*)(p + c0);
                    a[mf][1] = *(const uint32_t*)(p + 2048 + c0);
                    a[mf][2] = *(const uint32_t*)(p + c1);
                    a[mf][3] = *(const uint32_t*)(p + 2048 + c1);
                }
                #pragma unroll
                for (int nf = 0; nf < 8; nf++) {
                    const char* p = bB + nf * 2048;
                    uint32_t b0 = *(const uint32_t*)(p + c0);
                    uint32_t b1 = *(const uint32_t*)(p + c1);
                    #pragma unroll
                    for (int mf = 0; mf < 2; mf++)
                        mma_tf32(o[mf][nf], a[mf], b0, b1);
                }
            }
        }
    }

    // ---- epilogue: combine row sums, n = max(|sum|, exp(-m)), write O/n ----
    #pragma unroll
    for (int k = 0; k < 4; k++) {
        ssum[k] += __shfl_xor_sync(0xffffffffu, ssum[k], 1);
        ssum[k] += __shfl_xor_sync(0xffffffffu, ssum[k], 2);
    }
    if (laneC == 0) {
        #pragma unroll
        for (int k = 0; k < 4; k++) {
            int row = warp_m * 32 + (k >> 1) * 16 + (k & 1) * 8 + laneR;
            ss_sh[warp_n * 64 + row] = ssum[k];
        }
    }
    __syncthreads();
    float inv[4];
    #pragma unroll
    for (int k = 0; k < 4; k++) {
        int row = warp_m * 32 + (k >> 1) * 16 + (k & 1) * 8 + laneR;
        float tot = ss_sh[row] + ss_sh[64 + row] + ss_sh[128 + row] + ss_sh[192 + row];
        float mm = g_mm[bh * SS + t0 + row];
        inv[k] = 1.f / fmaxf(fabsf(tot), __expf(-mm));
    }
    #pragma unroll
    for (int mf = 0; mf < 2; mf++) {
        int r0 = t0 + warp_m * 32 + mf * 16 + laneR;
        float i0 = inv[mf * 2], i1 = inv[mf * 2 + 1];
        #pragma unroll
        for (int nf = 0; nf < 8; nf++) {
            int c = warp_n * 64 + nf * 8 + 2 * laneC;
            *(float2*)(g_h + qkvbase + (size_t)r0 * II + c) =
                make_float2(o[mf][nf][0] * i0, o[mf][nf][1] * i0);
            *(float2*)(g_h + qkvbase + (size_t)(r0 + 8) * II + c) =
                make_float2(o[mf][nf][2] * i1, o[mf][nf][3] * i1);
        }
    }
}

// ---------------- per-head norm + gn_g + skip*c_act + *silu(z) -------------
__global__ __launch_bounds__(256) void headgate_kernel(const float* __restrict__ gn,
                                                       const float* __restrict__ sk)
{
    int row = blockIdx.x;
    int tid = threadIdx.x;
    __shared__ float sh[16];
    __shared__ float stat[2];
    size_t base = (size_t)row * II;
    for (int h = 0; h < HH; h++) {
        float v = g_h[base + h*DHH + tid];
        float s = v, s2 = v*v;
        for (int o = 16; o; o >>= 1) {
            s  += __shfl_down_sync(0xffffffffu, s,  o);
            s2 += __shfl_down_sync(0xffffffffu, s2, o);
        }
        int wid = tid >> 5, lane = tid & 31;
        if (lane == 0) { sh[wid] = s; sh[8+wid] = s2; }
        __syncthreads();
        if (tid == 0) {
            float ts = 0.f, ts2 = 0.f;
            for (int w = 0; w < 8; w++) { ts += sh[w]; ts2 += sh[8+w]; }
            stat[0] = ts * (1.f/DHH); stat[1] = ts2 * (1.f/DHH);
        }
        __syncthreads();
        float mu = stat[0];
        float var = stat[1] - mu*mu;
        float rstd = rsqrtf(var + EPS);
        int c = h*DHH + tid;
        float hn = (v - mu) * rstd * gn[c];
        hn += sk[c] * g_cact[base + c];
        float z = g_up[(size_t)row * 2048 + II + c];
        hn *= z / (1.f + __expf(-z));
        g_h[base + c] = hn;
        __syncthreads();
    }
}

// ------------------------------- host -----------------------------------------
#define WT_PER   4718592
#define WT_UP(l)   (g_wT_ptr + (size_t)(l)*WT_PER)
#define WT_Q(l)    (g_wT_ptr + (size_t)(l)*WT_PER + 1048576)
#define WT_K(l)    (g_wT_ptr + (size_t)(l)*WT_PER + 2097152)
#define WT_V(l)    (g_wT_ptr + (size_t)(l)*WT_PER + 3145728)
#define WT_DOWN(l) (g_wT_ptr + (size_t)(l)*WT_PER + 4194304)
#define WT_FIN     (g_wT_ptr + (size_t)2*WT_PER)

static inline void launch_gemm(const float* A, int lda, const float* BT,
                               float* C, int ldc, int M, int N, int K,
                               const float* bias, const float* res, int ldres)
{
    dim3 grid(N / 128, M / 128);
    tf32gemm_kernel<<<grid, 256, GEMM_SMEM>>>(A, lda, BT, C, ldc, K, bias, res, ldres);
}

extern "C" void kernel_launch(void* const* d_in, const int* in_sizes, int n_in,
                              void* d_out, int out_size)
{
    (void)in_sizes; (void)n_in; (void)out_size;
    const float* x      = (const float*)d_in[0];
    const float* ln_g   = (const float*)d_in[1];
    const float* ln_b   = (const float*)d_in[2];
    const float* w_up   = (const float*)d_in[3];
    const float* conv_w = (const float*)d_in[4];
    const float* conv_b = (const float*)d_in[5];
    const float* wq     = (const float*)d_in[6];
    const float* wk     = (const float*)d_in[7];
    const float* wv     = (const float*)d_in[8];
    const float* w_i    = (const float*)d_in[9];
    const float* b_i    = (const float*)d_in[10];
    const float* w_f    = (const float*)d_in[11];
    const float* b_f    = (const float*)d_in[12];
    const float* skip   = (const float*)d_in[13];
    const float* gn_g   = (const float*)d_in[14];
    const float* w_down = (const float*)d_in[15];
    const float* b_down = (const float*)d_in[16];
    const float* w_fin  = (const float*)d_in[17];
    const float* b_fin  = (const float*)d_in[18];

    float *xn, *up, *cact, *q, *k, *v, *hb, *x1, *g_wT_ptr, *vT;
    cudaGetSymbolAddress((void**)&xn,   g_xn);
    cudaGetSymbolAddress((void**)&up,   g_up);
    cudaGetSymbolAddress((void**)&cact, g_cact);
    cudaGetSymbolAddress((void**)&q,    g_q);
    cudaGetSymbolAddress((void**)&k,    g_k);
    cudaGetSymbolAddress((void**)&v,    g_v);
    cudaGetSymbolAddress((void**)&hb,   g_h);
    cudaGetSymbolAddress((void**)&x1,   g_x1);
    cudaGetSymbolAddress((void**)&g_wT_ptr, g_wT);
    cudaGetSymbolAddress((void**)&vT,   g_vT);

    cudaFuncSetAttribute(tf32gemm_kernel, cudaFuncAttributeMaxDynamicSharedMemorySize,
                         GEMM_SMEM);
    cudaFuncSetAttribute(attn2_kernel, cudaFuncAttributeMaxDynamicSharedMemorySize,
                         ATT2_SMEM);

    // ---- transpose all weights (per-call; deterministic) ----
    for (int l = 0; l < 2; l++) {
        transpose_kernel<<<dim3(2048/32, 512/32), 256>>>(w_up  + (size_t)l*512*2048, WT_UP(l),   512, 2048);
        transpose_kernel<<<dim3(1024/32,1024/32), 256>>>(wq    + (size_t)l*II*II,    WT_Q(l),    1024, 1024);
        transpose_kernel<<<dim3(1024/32,1024/32), 256>>>(wk    + (size_t)l*II*II,    WT_K(l),    1024, 1024);
        transpose_kernel<<<dim3(1024/32,1024/32), 256>>>(wv    + (size_t)l*II*II,    WT_V(l),    1024, 1024);
        transpose_kernel<<<dim3( 512/32,1024/32), 256>>>(w_down+ (size_t)l*II*EE,    WT_DOWN(l), 1024, 512);
    }
    transpose_kernel<<<dim3(128/32, 512/32), 256>>>(w_fin, WT_FIN, 512, 128);

    const float* cur = x;
    for (int l = 0; l < 2; l++) {
        ln_kernel<<<BSR, 256>>>(cur, ln_g + l*EE, ln_b + l*EE, xn);
        launch_gemm(xn, EE, WT_UP(l), up, 2048, BSR, 2048, EE, nullptr, nullptr, 0);
        conv_silu_kernel<<<(BSR*II)/256, 256>>>(conv_w + l*KKC*II, conv_b + l*II);
        launch_gemm(cact, II,   WT_Q(l), q, II, BSR, II, II, nullptr, nullptr, 0);
        launch_gemm(cact, II,   WT_K(l), k, II, BSR, II, II, nullptr, nullptr, 0);
        launch_gemm(up,   2048, WT_V(l), v, II, BSR, II, II, nullptr, nullptr, 0);
        gates_kernel<<<BSR, 256>>>(w_i + (size_t)l*3*II*HH, b_i + l*HH,
                                   w_f + (size_t)l*3*II*HH, b_f + l*HH);
        cumsum_kernel<<<BB*HH, SS>>>();
        vtrans_kernel<<<dim3(SS/32, DHH/32, BB*HH), 256>>>(vT);
        attn2_kernel<<<dim3(BB*HH, SS/64), 256, ATT2_SMEM>>>(vT);
        headgate_kernel<<<BSR, 256>>>(gn_g + l*II, skip + l*II);
        launch_gemm(hb, II, WT_DOWN(l), x1, EE, BSR, EE, II, b_down + l*EE, cur, EE);
        cur = x1;
    }
    // final: (8192,512)@(512,128) + b_fin
    launch_gemm(x1, EE, WT_FIN, (float*)d_out, 128, BSR, 128, EE, b_fin, nullptr, 0);
}

// round 5
// speedup vs baseline: 6.0010x; 1.5032x over previous
#include <cuda_runtime.h>
#include <cstdint>
#include <math.h>

// Problem dims
#define BB   8
#define SS   1024
#define EE   512
#define II   1024
#define HH   4
#define DHH  256
#define KKC  4
#define BSR  (BB*SS)          // 8192 rows
#define EPS  1e-5f

// ---------------- scratch (static device memory; rewritten every call) ----------
__device__ float g_xn  [BSR*EE];          // tf32-rounded (up GEMM A)
__device__ float g_up  [BSR*2048];        // x_m = cols [0,1024), z = cols [1024,2048)
__device__ float g_cact[BSR*II];          // fp32 (headgate skip)
__device__ float g_ca32[BSR*II];          // tf32 copy (q/k GEMM A)
__device__ float g_xm32[BSR*II];          // tf32 dense x_m copy (v GEMM A)
__device__ float g_q   [BSR*II];
__device__ float g_k   [BSR*II];
__device__ float g_v   [BSR*II];
__device__ float g_h   [BSR*II];          // attn out -> headgate writes tf32 (down GEMM A)
__device__ float g_x1  [BSR*EE];          // fp32 residual stream
__device__ float g_x132[BSR*EE];          // tf32 copy (fin GEMM A)
__device__ float g_ipre[BB*HH*SS];
__device__ float g_fpre[BB*HH*SS];
__device__ float g_u   [BB*HH*SS];
__device__ float g_mx  [BB*HH*SS];
__device__ float g_mm  [BB*HH*SS];
__device__ float g_vT  [32*256*1024];     // V^T per (b,h), tf32-packed (32MB)
__device__ float g_w32 [9502720];         // tf32-rounded weights, original [K,N] layouts

__device__ __forceinline__ uint32_t f2tf32(float f) {
    uint32_t r;
    asm("cvt.rna.tf32.f32 %0, %1;" : "=r"(r) : "f"(f));
    return r;
}
__device__ __forceinline__ uint32_t smem_u32(const void* p) {
    uint32_t a;
    asm("{ .reg .u64 t; cvta.to.shared.u64 t, %1; cvt.u32.u64 %0, t; }" : "=r"(a) : "l"(p));
    return a;
}
__device__ __forceinline__ void cp_async16(uint32_t dst, const float* src) {
    asm volatile("cp.async.cg.shared.global [%0], [%1], 16;" :: "r"(dst), "l"(src));
}
#define CP_COMMIT() asm volatile("cp.async.commit_group;" ::: "memory")
#define CP_WAIT1()  asm volatile("cp.async.wait_group 1;"  ::: "memory")

__device__ __forceinline__ void mma_tf32(float* d, const uint32_t* a, uint32_t b0, uint32_t b1) {
    asm volatile("mma.sync.aligned.m16n8k8.row.col.f32.tf32.tf32.f32 "
        "{%0,%1,%2,%3}, {%4,%5,%6,%7}, {%8,%9}, {%0,%1,%2,%3};"
        : "+f"(d[0]), "+f"(d[1]), "+f"(d[2]), "+f"(d[3])
        : "r"(a[0]), "r"(a[1]), "r"(a[2]), "r"(a[3]), "r"(b0), "r"(b1));
}

// ================= tf32 mma.sync GEMM, cp.async 3-stage =========================
// C[M,N] = A[M,K] @ B[K,N]; A,B hold tf32-rounded bits. B in original [K,N] layout.
// CTA tile 128x128, BK=32, 256 thr = 8 warps (2m x 4n), warp tile 64x32.
// A smem: [m][k] 128B rows, chunk^(m&7) swizzle. B smem: [k][n] 512B rows,
// chunk^((k&3)<<1) swizzle (conflict-free fragment reads).

__device__ __forceinline__ void issue_tile(uint32_t sA, uint32_t sB,
        const float* A, int lda, const float* B, int ldb,
        int row0, int col0, int k0, int tid)
{
    const float* Ag = A + (size_t)row0 * lda + k0;
    const float* Bg = B + (size_t)k0 * ldb + col0;
    #pragma unroll
    for (int j = 0; j < 4; j++) {
        int i = tid + 256 * j;
        int r = i >> 3, c = i & 7;
        cp_async16(sA + (r << 7) + ((c ^ (r & 7)) << 4), Ag + (size_t)r * lda + (c << 2));
    }
    #pragma unroll
    for (int j = 0; j < 4; j++) {
        int i = tid + 256 * j;
        int k = i >> 5, c = i & 31;
        cp_async16(sB + (k << 9) + ((c ^ ((k & 3) << 1)) << 4), Bg + (size_t)k * ldb + (c << 2));
    }
}

__device__ __forceinline__ void compute_tile(const char* sA, const char* sB,
        float d[4][4][4], int warp_m, int warp_n, int laneR, int laneC)
{
    const char* aBase = sA + (warp_m * 64 + laneR) * 128 + laneC * 4;
    const char* bBase = sB + laneC * 512 + ((laneR & 3) << 2);
    int cbase = warp_n * 8 + (laneR >> 2);
    #pragma unroll
    for (int ks = 0; ks < 4; ks++) {
        uint32_t c0 = (uint32_t)(((2 * ks)     ^ laneR) << 4);
        uint32_t c1 = (uint32_t)(((2 * ks + 1) ^ laneR) << 4);
        uint32_t a[4][4];
        #pragma unroll
        for (int mf = 0; mf < 4; mf++) {
            const char* p = aBase + mf * 2048;
            a[mf][0] = *(const uint32_t*)(p + c0);
            a[mf][1] = *(const uint32_t*)(p + 1024 + c0);
            a[mf][2] = *(const uint32_t*)(p + c1);
            a[mf][3] = *(const uint32_t*)(p + 1024 + c1);
        }
        const char* br = bBase + ks * 4096;
        #pragma unroll
        for (int nf = 0; nf < 4; nf++) {
            uint32_t cc = (uint32_t)(((cbase + 2 * nf) ^ (laneC << 1)) << 4);
            uint32_t b0 = *(const uint32_t*)(br + cc);
            uint32_t b1 = *(const uint32_t*)(br + 2048 + cc);
            #pragma unroll
            for (int mf = 0; mf < 4; mf++)
                mma_tf32(d[mf][nf], a[mf], b0, b1);
        }
    }
}

#define GEMM_SMEM (3 * 32768)

__global__ __launch_bounds__(256) void tf32gemm_kernel(
    const float* __restrict__ A, int lda,
    const float* __restrict__ B, int ldb,
    float* __restrict__ C, int ldc, int K,
    const float* __restrict__ bias,
    const float* __restrict__ res, int ldres,
    float* __restrict__ C2)
{
    extern __shared__ __align__(128) char sm[];
    uint32_t sbase = smem_u32(sm);

    int tid = threadIdx.x;
    int wid = tid >> 5, lane = tid & 31;
    int laneR = lane >> 2, laneC = lane & 3;
    int warp_m = wid & 1, warp_n = wid >> 1;
    int row0 = blockIdx.y * 128, col0 = blockIdx.x * 128;

    float d[4][4][4];
    #pragma unroll
    for (int i = 0; i < 4; i++)
        #pragma unroll
        for (int j = 0; j < 4; j++)
            #pragma unroll
            for (int u = 0; u < 4; u++) d[i][j][u] = 0.f;

    const int NK = K >> 5;

    issue_tile(sbase, sbase + 16384, A, lda, B, ldb, row0, col0, 0, tid);
    CP_COMMIT();
    issue_tile(sbase + 32768, sbase + 49152, A, lda, B, ldb, row0, col0, 32, tid);
    CP_COMMIT();

    #pragma unroll 1
    for (int kt = 0; kt < NK; kt++) {
        CP_WAIT1();
        __syncthreads();
        if (kt + 2 < NK) {
            int s = (kt + 2) % 3;
            issue_tile(sbase + s * 32768, sbase + s * 32768 + 16384,
                       A, lda, B, ldb, row0, col0, (kt + 2) << 5, tid);
        }
        CP_COMMIT();
        int b = kt % 3;
        compute_tile(sm + b * 32768, sm + b * 32768 + 16384, d, warp_m, warp_n, laneR, laneC);
    }

    #pragma unroll
    for (int mf = 0; mf < 4; mf++) {
        int r = row0 + warp_m * 64 + mf * 16 + laneR;
        #pragma unroll
        for (int nf = 0; nf < 4; nf++) {
            int cc = col0 + warp_n * 32 + nf * 8 + 2 * laneC;
            float2 v0 = make_float2(d[mf][nf][0], d[mf][nf][1]);
            float2 v1 = make_float2(d[mf][nf][2], d[mf][nf][3]);
            if (bias) {
                float2 bv = *(const float2*)(bias + cc);
                v0.x += bv.x; v0.y += bv.y;
                v1.x += bv.x; v1.y += bv.y;
            }
            if (res) {
                float2 r0 = *(const float2*)(res + (size_t)r * ldres + cc);
                float2 r1 = *(const float2*)(res + (size_t)(r + 8) * ldres + cc);
                v0.x += r0.x; v0.y += r0.y;
                v1.x += r1.x; v1.y += r1.y;
            }
            *(float2*)(C + (size_t)r * ldc + cc)       = v0;
            *(float2*)(C + (size_t)(r + 8) * ldc + cc) = v1;
            if (C2) {
                uint2 t0 = make_uint2(f2tf32(v0.x), f2tf32(v0.y));
                uint2 t1 = make_uint2(f2tf32(v1.x), f2tf32(v1.y));
                *(uint2*)(C2 + (size_t)r * ldc + cc)       = t0;
                *(uint2*)(C2 + (size_t)(r + 8) * ldc + cc) = t1;
            }
        }
    }
}

// ---------------- weight convert: cvt.rna all weights into g_w32 ---------------
// float4 segments: up 524288 | q 524288 | k 524288 | v 524288 | down 262144 | fin 16384
__global__ __launch_bounds__(256) void wconv_kernel(
    const float* __restrict__ up, const float* __restrict__ q,
    const float* __restrict__ k,  const float* __restrict__ v,
    const float* __restrict__ dn, const float* __restrict__ fin,
    float* __restrict__ out)
{
    int i = blockIdx.x * 256 + threadIdx.x;
    const float* src; int off;
    if      (i <  524288) { src = up;  off = i; }
    else if (i < 1048576) { src = q;   off = i -  524288; }
    else if (i < 1572864) { src = k;   off = i - 1048576; }
    else if (i < 2097152) { src = v;   off = i - 1572864; }
    else if (i < 2359296) { src = dn;  off = i - 2097152; }
    else                  { src = fin; off = i - 2359296; }
    float4 x = ((const float4*)src)[off];
    uint4 y = make_uint4(f2tf32(x.x), f2tf32(x.y), f2tf32(x.z), f2tf32(x.w));
    ((uint4*)out)[i] = y;
}

// ---------------- V transpose per (b,h): g_v -> g_vT[bh][d][t], tf32-packed ----
__global__ __launch_bounds__(256) void vtrans_kernel(float* __restrict__ vT)
{
    __shared__ float t[32][33];
    int bh = blockIdx.z;
    int b = bh >> 2, h = bh & 3;
    int t0 = blockIdx.x * 32, d0 = blockIdx.y * 32;
    int tx = threadIdx.x & 31, ty = threadIdx.x >> 5;
    #pragma unroll
    for (int j = 0; j < 32; j += 8)
        t[ty + j][tx] = g_v[(size_t)(b * SS + t0 + ty + j) * II + h * DHH + d0 + tx];
    __syncthreads();
    #pragma unroll
    for (int j = 0; j < 32; j += 8)
        vT[((size_t)bh * DHH + d0 + ty + j) * SS + t0 + tx] =
            __uint_as_float(f2tf32(t[tx][ty + j]));
}

// ---------------- LayerNorm over E=512 (stores tf32 bits; GEMM-only consumer) --
__global__ __launch_bounds__(256) void ln_kernel(const float* __restrict__ x,
                                                 const float* __restrict__ g,
                                                 const float* __restrict__ b,
                                                 float* __restrict__ y)
{
    int row = blockIdx.x;
    const float* xr = x + (size_t)row * EE;
    float s = 0.f, s2 = 0.f;
    for (int c = threadIdx.x; c < EE; c += 256) { float v = xr[c]; s += v; s2 += v*v; }
    __shared__ float sh[64];
    for (int o = 16; o; o >>= 1) {
        s  += __shfl_down_sync(0xffffffffu, s,  o);
        s2 += __shfl_down_sync(0xffffffffu, s2, o);
    }
    int wid = threadIdx.x >> 5, lane = threadIdx.x & 31;
    if (lane == 0) { sh[wid] = s; sh[32+wid] = s2; }
    __syncthreads();
    if (threadIdx.x == 0) {
        float ts = 0.f, ts2 = 0.f;
        for (int w = 0; w < 8; w++) { ts += sh[w]; ts2 += sh[32+w]; }
        sh[0] = ts; sh[32] = ts2;
    }
    __syncthreads();
    float mu  = sh[0]  * (1.f/EE);
    float var = sh[32] * (1.f/EE) - mu*mu;
    float rstd = rsqrtf(var + EPS);
    float* yr = y + (size_t)row * EE;
    for (int c = threadIdx.x; c < EE; c += 256)
        yr[c] = __uint_as_float(f2tf32((xr[c] - mu) * rstd * g[c] + b[c]));
}

// ---------------- causal depthwise conv (K=4) + SiLU (+ tf32 copies) -----------
__global__ __launch_bounds__(256) void conv_silu_kernel(const float* __restrict__ cw,
                                                        const float* __restrict__ cb)
{
    int idx = blockIdx.x * 256 + threadIdx.x;
    int c   = idx & (II - 1);
    int row = idx >> 10;
    int t   = row & (SS - 1);
    float acc = cb[c];
    const float* base = g_up + (size_t)row * 2048 + c;
    #pragma unroll
    for (int j = 0; j < KKC; j++) {
        int tt = t - (KKC - 1) + j;
        if (tt >= 0) acc += base[(j - (KKC - 1)) * 2048] * cw[j * II + c];
    }
    float sv = acc / (1.f + __expf(-acc));
    g_cact[idx] = sv;
    g_ca32[idx] = __uint_as_float(f2tf32(sv));
    g_xm32[idx] = __uint_as_float(f2tf32(base[0]));
}

// ---------------- gate projections: ipre/fpre[b,h,t] ---------------------------
__global__ __launch_bounds__(256) void gates_kernel(const float* __restrict__ wi,
                                                    const float* __restrict__ bi,
                                                    const float* __restrict__ wf,
                                                    const float* __restrict__ bf)
{
    int row = blockIdx.x;
    const float* q = g_q + (size_t)row * II;
    const float* k = g_k + (size_t)row * II;
    const float* v = g_v + (size_t)row * II;
    float ai[HH] = {0,0,0,0}, af[HH] = {0,0,0,0};
    for (int d = threadIdx.x; d < II; d += 256) {
        float qv = q[d], kv = k[d], vv = v[d];
        const float* wiq = wi + (size_t)d * HH;
        const float* wik = wi + (size_t)(II + d) * HH;
        const float* wiv = wi + (size_t)(2*II + d) * HH;
        const float* wfq = wf + (size_t)d * HH;
        const float* wfk = wf + (size_t)(II + d) * HH;
        const float* wfv = wf + (size_t)(2*II + d) * HH;
        #pragma unroll
        for (int h2 = 0; h2 < HH; h2++) {
            ai[h2] += qv*wiq[h2] + kv*wik[h2] + vv*wiv[h2];
            af[h2] += qv*wfq[h2] + kv*wfk[h2] + vv*wfv[h2];
        }
    }
    __shared__ float red[64];
    int lane = threadIdx.x & 31, wid = threadIdx.x >> 5;
    #pragma unroll
    for (int s = 0; s < 8; s++) {
        float x = (s < 4) ? ai[s] : af[s-4];
        for (int o = 16; o; o >>= 1) x += __shfl_down_sync(0xffffffffu, x, o);
        if (lane == 0) red[s * 8 + wid] = x;
    }
    __syncthreads();
    if (threadIdx.x < 64) {
        float x = red[threadIdx.x];
        x += __shfl_down_sync(0xffffffffu, x, 4, 8);
        x += __shfl_down_sync(0xffffffffu, x, 2, 8);
        x += __shfl_down_sync(0xffffffffu, x, 1, 8);
        if ((threadIdx.x & 7) == 0) {
            int s = threadIdx.x >> 3;
            int b = row >> 10, t = row & (SS - 1);
            if (s < 4) g_ipre[((size_t)b*HH + s)     * SS + t] = x + bi[s];
            else       g_fpre[((size_t)b*HH + (s-4)) * SS + t] = x + bf[s-4];
        }
    }
}

// ---------------- gate scan: lfc, u = ipre - lfc, M = runmax u, m = lfc + M -----
__global__ __launch_bounds__(1024) void cumsum_kernel()
{
    int bh = blockIdx.x;
    int t  = threadIdx.x;
    float f  = g_fpre[bh * SS + t];
    float lf = (f > 0.f) ? -log1pf(__expf(-f)) : f - log1pf(__expf(f));
    __shared__ float sc[SS];
    sc[t] = lf;
    __syncthreads();
    for (int off = 1; off < SS; off <<= 1) {
        float v = (t >= off) ? sc[t - off] : 0.f;
        __syncthreads();
        sc[t] += v;
        __syncthreads();
    }
    float lfc = sc[t];
    float u = g_ipre[bh * SS + t] - lfc;
    g_u[bh * SS + t] = u;
    __syncthreads();
    sc[t] = u;
    __syncthreads();
    for (int off = 1; off < SS; off <<= 1) {
        float v = (t >= off) ? sc[t - off] : -1e30f;
        __syncthreads();
        sc[t] = fmaxf(sc[t], v);
        __syncthreads();
    }
    float M = sc[t];
    g_mx[bh * SS + t] = M;
    g_mm[bh * SS + t] = lfc + M;
}

// ---------------- tensor-core causal mLSTM attention ---------------------------
#define ATT2_SMEM 214272
__global__ __launch_bounds__(256) void attn2_kernel(const float* __restrict__ vT)
{
    extern __shared__ __align__(128) char sm2[];
    char*  Qs    = sm2;
    char*  Ks    = sm2 + 65536;
    char*  Vs    = sm2 + 131072;
    char*  Ps    = sm2 + 196608;
    float* u_sh  = (float*)(sm2 + 212992);
    float* ss_sh = (float*)(sm2 + 213248);

    int bh = blockIdx.x;
    int tb = (int)gridDim.y - 1 - (int)blockIdx.y;
    int b = bh >> 2, h = bh & 3;
    int tid = threadIdx.x;
    int wid = tid >> 5, lane = tid & 31;
    int laneR = lane >> 2, laneC = lane & 3;
    int warp_m = wid & 1, warp_n = wid >> 1;
    int t0 = tb * 64;
    size_t qkvbase = ((size_t)b * SS) * II + (size_t)h * DHH;
    const float* vTb = vT + (size_t)bh * DHH * SS;

    #pragma unroll
    for (int j = 0; j < 16; j++) {
        int i = tid + 256 * j;
        int r = i >> 6, c = i & 63;
        float4 v = *(const float4*)(g_q + qkvbase + (size_t)(t0 + r) * II + (c << 2));
        uint4 w = make_uint4(f2tf32(v.x * 0.0625f), f2tf32(v.y * 0.0625f),
                             f2tf32(v.z * 0.0625f), f2tf32(v.w * 0.0625f));
        *(uint4*)(Qs + r * 1024 + ((c ^ (r & 7)) << 4)) = w;
    }

    float Mr[4], ssum[4];
    #pragma unroll
    for (int k = 0; k < 4; k++) {
        int row = warp_m * 32 + (k >> 1) * 16 + (k & 1) * 8 + laneR;
        Mr[k] = g_mx[bh * SS + t0 + row];
        ssum[k] = 0.f;
    }

    float o[2][8][4];
    #pragma unroll
    for (int mf = 0; mf < 2; mf++)
        #pragma unroll
        for (int nf = 0; nf < 8; nf++)
            #pragma unroll
            for (int u = 0; u < 4; u++) o[mf][nf][u] = 0.f;

    #pragma unroll 1
    for (int sb = 0; sb <= tb; sb++) {
        int s0 = sb * 64;
        __syncthreads();
        #pragma unroll
        for (int j = 0; j < 16; j++) {
            int i = tid + 256 * j;
            int r = i >> 6, c = i & 63;
            float4 v = *(const float4*)(g_k + qkvbase + (size_t)(s0 + r) * II + (c << 2));
            uint4 w = make_uint4(f2tf32(v.x), f2tf32(v.y), f2tf32(v.z), f2tf32(v.w));
            *(uint4*)(Ks + r * 1024 + ((c ^ (r & 7)) << 4)) = w;
        }
        #pragma unroll
        for (int j = 0; j < 16; j++) {
            int i = tid + 256 * j;
            int r = i >> 4, c = i & 15;
            float4 v = *(const float4*)(vTb + (size_t)r * SS + s0 + (c << 2));
            *(float4*)(Vs + (r << 8) + ((c ^ (r & 7)) << 4)) = v;
        }
        if (tid < 64) u_sh[tid] = g_u[bh * SS + s0 + tid];
        __syncthreads();

        float s8[2][2][4];
        #pragma unroll
        for (int mf = 0; mf < 2; mf++)
            #pragma unroll
            for (int nf = 0; nf < 2; nf++)
                #pragma unroll
                for (int u = 0; u < 4; u++) s8[mf][nf][u] = 0.f;
        {
            const char* aB = Qs + (warp_m * 32 + laneR) * 1024 + laneC * 4;
            const char* bB = Ks + (warp_n * 16 + laneR) * 1024 + laneC * 4;
            #pragma unroll
            for (int ks = 0; ks < 32; ks++) {
                uint32_t c0 = (uint32_t)(((2 * ks)     ^ laneR) << 4);
                uint32_t c1 = (uint32_t)(((2 * ks + 1) ^ laneR) << 4);
                uint32_t a[2][4], bf[2][2];
                #pragma unroll
                for (int mf = 0; mf < 2; mf++) {
                    const char* p = aB + mf * 16384;
                    a[mf][0] = *(const uint32_t*)(p + c0);
                    a[mf][1] = *(const uint32_t*)(p + 8192 + c0);
                    a[mf][2] = *(const uint32_t*)(p + c1);
                    a[mf][3] = *(const uint32_t*)(p + 8192 + c1);
                }
                #pragma unroll
                for (int nf = 0; nf < 2; nf++) {
                    const char* p = bB + nf * 8192;
                    bf[nf][0] = *(const uint32_t*)(p + c0);
                    bf[nf][1] = *(const uint32_t*)(p + c1);
                }
                #pragma unroll
                for (int mf = 0; mf < 2; mf++)
                    #pragma unroll
                    for (int nf = 0; nf < 2; nf++)
                        mma_tf32(s8[mf][nf], a[mf], bf[nf][0], bf[nf][1]);
            }
        }

        bool diag = (sb == tb);
        #pragma unroll
        for (int mf = 0; mf < 2; mf++) {
            #pragma unroll
            for (int e = 0; e < 2; e++) {
                int row = warp_m * 32 + mf * 16 + e * 8 + laneR;
                int tg = t0 + row;
                float M = Mr[mf * 2 + e];
                #pragma unroll
                for (int nf = 0; nf < 2; nf++) {
                    int cb = warp_n * 16 + nf * 8 + 2 * laneC;
                    float d0 = s8[mf][nf][2 * e], d1 = s8[mf][nf][2 * e + 1];
                    float w0 = (!diag || (s0 + cb)     <= tg) ? __expf(u_sh[cb]     - M) : 0.f;
                    float w1 = (!diag || (s0 + cb + 1) <= tg) ? __expf(u_sh[cb + 1] - M) : 0.f;
                    uint2 pk = make_uint2(f2tf32(d0 * w0), f2tf32(d1 * w1));
                    ssum[mf * 2 + e] += __uint_as_float(pk.x) + __uint_as_float(pk.y);
                    *(uint2*)(Ps + (row << 8) + (((cb >> 2) ^ (row & 7)) << 4)
                              + ((cb & 3) << 2)) = pk;
                }
            }
        }
        __syncthreads();

        {
            const char* aB = Ps + (warp_m * 32 + laneR) * 256 + laneC * 4;
            const char* bB = Vs + (warp_n * 64 + laneR) * 256 + laneC * 4;
            #pragma unroll
            for (int ks = 0; ks < 8; ks++) {
                uint32_t c0 = (uint32_t)(((2 * ks)     ^ laneR) << 4);
                uint32_t c1 = (uint32_t)(((2 * ks + 1) ^ laneR) << 4);
                uint32_t a[2][4];
                #pragma unroll
                for (int mf = 0; mf < 2; mf++) {
                    const char* p = aB + mf * 4096;
                    a[mf][0] = *(const uint32_t*)(p + c0);
                    a[mf][1] = *(const uint32_t*)(p + 2048 + c0);
                    a[mf][2] = *(const uint32_t*)(p + c1);
                    a[mf][3] = *(const uint32_t*)(p + 2048 + c1);
                }
                #pragma unroll
                for (int nf = 0; nf < 8; nf++) {
                    const char* p = bB + nf * 2048;
                    uint32_t b0 = *(const uint32_t*)(p + c0);
                    uint32_t b1 = *(const uint32_t*)(p + c1);
                    #pragma unroll
                    for (int mf = 0; mf < 2; mf++)
                        mma_tf32(o[mf][nf], a[mf], b0, b1);
                }
            }
        }
    }

    #pragma unroll
    for (int k = 0; k < 4; k++) {
        ssum[k] += __shfl_xor_sync(0xffffffffu, ssum[k], 1);
        ssum[k] += __shfl_xor_sync(0xffffffffu, ssum[k], 2);
    }
    if (laneC == 0) {
        #pragma unroll
        for (int k = 0; k < 4; k++) {
            int row = warp_m * 32 + (k >> 1) * 16 + (k & 1) * 8 + laneR;
            ss_sh[warp_n * 64 + row] = ssum[k];
        }
    }
    __syncthreads();
    float inv[4];
    #pragma unroll
    for (int k = 0; k < 4; k++) {
        int row = warp_m * 32 + (k >> 1) * 16 + (k & 1) * 8 + laneR;
        float tot = ss_sh[row] + ss_sh[64 + row] + ss_sh[128 + row] + ss_sh[192 + row];
        float mm = g_mm[bh * SS + t0 + row];
        inv[k] = 1.f / fmaxf(fabsf(tot), __expf(-mm));
    }
    #pragma unroll
    for (int mf = 0; mf < 2; mf++) {
        int r0 = t0 + warp_m * 32 + mf * 16 + laneR;
        float i0 = inv[mf * 2], i1 = inv[mf * 2 + 1];
        #pragma unroll
        for (int nf = 0; nf < 8; nf++) {
            int c = warp_n * 64 + nf * 8 + 2 * laneC;
            *(float2*)(g_h + qkvbase + (size_t)r0 * II + c) =
                make_float2(o[mf][nf][0] * i0, o[mf][nf][1] * i0);
            *(float2*)(g_h + qkvbase + (size_t)(r0 + 8) * II + c) =
                make_float2(o[mf][nf][2] * i1, o[mf][nf][3] * i1);
        }
    }
}

// ---------------- per-head norm + gn_g + skip*c_act + *silu(z) (stores tf32) ---
__global__ __launch_bounds__(256) void headgate_kernel(const float* __restrict__ gn,
                                                       const float* __restrict__ sk)
{
    int row = blockIdx.x;
    int tid = threadIdx.x;
    __shared__ float sh[16];
    __shared__ float stat[2];
    size_t base = (size_t)row * II;
    for (int h = 0; h < HH; h++) {
        float v = g_h[base + h*DHH + tid];
        float s = v, s2 = v*v;
        for (int o = 16; o; o >>= 1) {
            s  += __shfl_down_sync(0xffffffffu, s,  o);
            s2 += __shfl_down_sync(0xffffffffu, s2, o);
        }
        int wid = tid >> 5, lane = tid & 31;
        if (lane == 0) { sh[wid] = s; sh[8+wid] = s2; }
        __syncthreads();
        if (tid == 0) {
            float ts = 0.f, ts2 = 0.f;
            for (int w = 0; w < 8; w++) { ts += sh[w]; ts2 += sh[8+w]; }
            stat[0] = ts * (1.f/DHH); stat[1] = ts2 * (1.f/DHH);
        }
        __syncthreads();
        float mu = stat[0];
        float var = stat[1] - mu*mu;
        float rstd = rsqrtf(var + EPS);
        int c = h*DHH + tid;
        float hn = (v - mu) * rstd * gn[c];
        hn += sk[c] * g_cact[base + c];
        float z = g_up[(size_t)row * 2048 + II + c];
        hn *= z / (1.f + __expf(-z));
        g_h[base + c] = __uint_as_float(f2tf32(hn));
        __syncthreads();
    }
}

// ------------------------------- host -----------------------------------------
// g_w32 float offsets
#define W32_UP(l)   (w32 + (size_t)(l)*1048576)
#define W32_Q(l)    (w32 + 2097152 + (size_t)(l)*1048576)
#define W32_K(l)    (w32 + 4194304 + (size_t)(l)*1048576)
#define W32_V(l)    (w32 + 6291456 + (size_t)(l)*1048576)
#define W32_DOWN(l) (w32 + 8388608 + (size_t)(l)*524288)
#define W32_FIN     (w32 + 9437184)

static inline void launch_gemm(const float* A, int lda, const float* B, int ldb,
                               float* C, int ldc, int M, int N, int K,
                               const float* bias, const float* res, int ldres,
                               float* C2 = nullptr)
{
    dim3 grid(N / 128, M / 128);
    tf32gemm_kernel<<<grid, 256, GEMM_SMEM>>>(A, lda, B, ldb, C, ldc, K,
                                              bias, res, ldres, C2);
}

extern "C" void kernel_launch(void* const* d_in, const int* in_sizes, int n_in,
                              void* d_out, int out_size)
{
    (void)in_sizes; (void)n_in; (void)out_size;
    const float* x      = (const float*)d_in[0];
    const float* ln_g   = (const float*)d_in[1];
    const float* ln_b   = (const float*)d_in[2];
    const float* w_up   = (const float*)d_in[3];
    const float* conv_w = (const float*)d_in[4];
    const float* conv_b = (const float*)d_in[5];
    const float* wq     = (const float*)d_in[6];
    const float* wk     = (const float*)d_in[7];
    const float* wv     = (const float*)d_in[8];
    const float* w_i    = (const float*)d_in[9];
    const float* b_i    = (const float*)d_in[10];
    const float* w_f    = (const float*)d_in[11];
    const float* b_f    = (const float*)d_in[12];
    const float* skip   = (const float*)d_in[13];
    const float* gn_g   = (const float*)d_in[14];
    const float* w_down = (const float*)d_in[15];
    const float* b_down = (const float*)d_in[16];
    const float* w_fin  = (const float*)d_in[17];
    const float* b_fin  = (const float*)d_in[18];

    float *xn, *up, *ca32, *xm32, *hb, *x1, *x132, *w32, *vT;
    cudaGetSymbolAddress((void**)&xn,   g_xn);
    cudaGetSymbolAddress((void**)&up,   g_up);
    cudaGetSymbolAddress((void**)&ca32, g_ca32);
    cudaGetSymbolAddress((void**)&xm32, g_xm32);
    cudaGetSymbolAddress((void**)&hb,   g_h);
    cudaGetSymbolAddress((void**)&x1,   g_x1);
    cudaGetSymbolAddress((void**)&x132, g_x132);
    cudaGetSymbolAddress((void**)&w32,  g_w32);
    cudaGetSymbolAddress((void**)&vT,   g_vT);
    float *qb, *kb, *vb;
    cudaGetSymbolAddress((void**)&qb, g_q);
    cudaGetSymbolAddress((void**)&kb, g_k);
    cudaGetSymbolAddress((void**)&vb, g_v);

    cudaFuncSetAttribute(tf32gemm_kernel, cudaFuncAttributeMaxDynamicSharedMemorySize,
                         GEMM_SMEM);
    cudaFuncSetAttribute(attn2_kernel, cudaFuncAttributeMaxDynamicSharedMemorySize,
                         ATT2_SMEM);

    // weights -> tf32 once (original layouts preserved)
    wconv_kernel<<<9280, 256>>>(w_up, wq, wk, wv, w_down, w_fin, w32);

    const float* cur = x;
    for (int l = 0; l < 2; l++) {
        ln_kernel<<<BSR, 256>>>(cur, ln_g + l*EE, ln_b + l*EE, xn);
        launch_gemm(xn, EE, W32_UP(l), 2048, up, 2048, BSR, 2048, EE,
                    nullptr, nullptr, 0);
        conv_silu_kernel<<<(BSR*II)/256, 256>>>(conv_w + l*KKC*II, conv_b + l*II);
        launch_gemm(ca32, II, W32_Q(l), II, qb, II, BSR, II, II, nullptr, nullptr, 0);
        launch_gemm(ca32, II, W32_K(l), II, kb, II, BSR, II, II, nullptr, nullptr, 0);
        launch_gemm(xm32, II, W32_V(l), II, vb, II, BSR, II, II, nullptr, nullptr, 0);
        gates_kernel<<<BSR, 256>>>(w_i + (size_t)l*3*II*HH, b_i + l*HH,
                                   w_f + (size_t)l*3*II*HH, b_f + l*HH);
        cumsum_kernel<<<BB*HH, SS>>>();
        vtrans_kernel<<<dim3(SS/32, DHH/32, BB*HH), 256>>>(vT);
        attn2_kernel<<<dim3(BB*HH, SS/64), 256, ATT2_SMEM>>>(vT);
        headgate_kernel<<<BSR, 256>>>(gn_g + l*II, skip + l*II);
        launch_gemm(hb, II, W32_DOWN(l), EE, x1, EE, BSR, EE, II,
                    b_down + l*EE, cur, EE, x132);
        cur = x1;
    }
    // final: (8192,512)@(512,128) + b_fin
    launch_gemm(x132, EE, W32_FIN, 128, (float*)d_out, 128, BSR, 128, EE,
                b_fin, nullptr, 0);
}

// round 6
// speedup vs baseline: 6.6798x; 1.1131x over previous
#include <cuda_runtime.h>
#include <cstdint>
#include <math.h>

// Problem dims
#define BB   8
#define SS   1024
#define EE   512
#define II   1024
#define HH   4
#define DHH  256
#define KKC  4
#define BSR  (BB*SS)          // 8192 rows
#define EPS  1e-5f

// ---------------- scratch (static device memory; rewritten every call) ----------
__device__ float g_xn  [BSR*EE];          // tf32-rounded (up GEMM A)
__device__ float g_up  [BSR*2048];        // x_m = cols [0,1024), z = cols [1024,2048)
__device__ float g_cact[BSR*II];          // fp32 (headgate skip)
__device__ float g_ca32[BSR*II];          // tf32 copy (q/k GEMM A)
__device__ float g_xm32[BSR*II];          // tf32 dense x_m copy (v GEMM A)
__device__ float g_q   [BSR*II];
__device__ float g_k   [BSR*II];
__device__ float g_v   [BSR*II];
__device__ float g_q32 [BSR*II];          // tf32 copy of q (attn)
__device__ float g_k32 [BSR*II];          // tf32 copy of k (attn)
__device__ float g_h   [BSR*II];          // attn out -> headgate writes tf32 (down GEMM A)
__device__ float g_x1  [BSR*EE];          // fp32 residual stream
__device__ float g_x132[BSR*EE];          // tf32 copy (fin GEMM A)
__device__ float g_ipre[BB*HH*SS];
__device__ float g_fpre[BB*HH*SS];
__device__ float g_u   [BB*HH*SS];
__device__ float g_mx  [BB*HH*SS];
__device__ float g_mm  [BB*HH*SS];
__device__ float g_vT  [32*256*1024];     // V^T per (b,h), tf32-packed (32MB)
__device__ float g_w32 [9502720];         // tf32-rounded weights, original [K,N] layouts

__device__ __forceinline__ uint32_t f2tf32(float f) {
    uint32_t r;
    asm("cvt.rna.tf32.f32 %0, %1;" : "=r"(r) : "f"(f));
    return r;
}
__device__ __forceinline__ uint32_t smem_u32(const void* p) {
    uint32_t a;
    asm("{ .reg .u64 t; cvta.to.shared.u64 t, %1; cvt.u32.u64 %0, t; }" : "=r"(a) : "l"(p));
    return a;
}
__device__ __forceinline__ void cp_async16(uint32_t dst, const float* src) {
    asm volatile("cp.async.cg.shared.global [%0], [%1], 16;" :: "r"(dst), "l"(src));
}
#define CP_COMMIT() asm volatile("cp.async.commit_group;" ::: "memory")
#define CP_WAIT1()  asm volatile("cp.async.wait_group 1;"  ::: "memory")
#define CP_WAIT0()  asm volatile("cp.async.wait_group 0;"  ::: "memory")

__device__ __forceinline__ void mma_tf32(float* d, const uint32_t* a, uint32_t b0, uint32_t b1) {
    asm volatile("mma.sync.aligned.m16n8k8.row.col.f32.tf32.tf32.f32 "
        "{%0,%1,%2,%3}, {%4,%5,%6,%7}, {%8,%9}, {%0,%1,%2,%3};"
        : "+f"(d[0]), "+f"(d[1]), "+f"(d[2]), "+f"(d[3])
        : "r"(a[0]), "r"(a[1]), "r"(a[2]), "r"(a[3]), "r"(b0), "r"(b1));
}

// ================= tf32 mma.sync GEMM, cp.async 3-stage =========================
__device__ __forceinline__ void issue_tile(uint32_t sA, uint32_t sB,
        const float* A, int lda, const float* B, int ldb,
        int row0, int col0, int k0, int tid)
{
    const float* Ag = A + (size_t)row0 * lda + k0;
    const float* Bg = B + (size_t)k0 * ldb + col0;
    #pragma unroll
    for (int j = 0; j < 4; j++) {
        int i = tid + 256 * j;
        int r = i >> 3, c = i & 7;
        cp_async16(sA + (r << 7) + ((c ^ (r & 7)) << 4), Ag + (size_t)r * lda + (c << 2));
    }
    #pragma unroll
    for (int j = 0; j < 4; j++) {
        int i = tid + 256 * j;
        int k = i >> 5, c = i & 31;
        cp_async16(sB + (k << 9) + ((c ^ ((k & 3) << 1)) << 4), Bg + (size_t)k * ldb + (c << 2));
    }
}

__device__ __forceinline__ void compute_tile(const char* sA, const char* sB,
        float d[4][4][4], int warp_m, int warp_n, int laneR, int laneC)
{
    const char* aBase = sA + (warp_m * 64 + laneR) * 128 + laneC * 4;
    const char* bBase = sB + laneC * 512 + ((laneR & 3) << 2);
    int cbase = warp_n * 8 + (laneR >> 2);
    #pragma unroll
    for (int ks = 0; ks < 4; ks++) {
        uint32_t c0 = (uint32_t)(((2 * ks)     ^ laneR) << 4);
        uint32_t c1 = (uint32_t)(((2 * ks + 1) ^ laneR) << 4);
        uint32_t a[4][4];
        #pragma unroll
        for (int mf = 0; mf < 4; mf++) {
            const char* p = aBase + mf * 2048;
            a[mf][0] = *(const uint32_t*)(p + c0);
            a[mf][1] = *(const uint32_t*)(p + 1024 + c0);
            a[mf][2] = *(const uint32_t*)(p + c1);
            a[mf][3] = *(const uint32_t*)(p + 1024 + c1);
        }
        const char* br = bBase + ks * 4096;
        #pragma unroll
        for (int nf = 0; nf < 4; nf++) {
            uint32_t cc = (uint32_t)(((cbase + 2 * nf) ^ (laneC << 1)) << 4);
            uint32_t b0 = *(const uint32_t*)(br + cc);
            uint32_t b1 = *(const uint32_t*)(br + 2048 + cc);
            #pragma unroll
            for (int mf = 0; mf < 4; mf++)
                mma_tf32(d[mf][nf], a[mf], b0, b1);
        }
    }
}

#define GEMM_SMEM (3 * 32768)

__global__ __launch_bounds__(256) void tf32gemm_kernel(
    const float* __restrict__ A, int lda,
    const float* __restrict__ B, int ldb,
    float* __restrict__ C, int ldc, int K,
    const float* __restrict__ bias,
    const float* __restrict__ res, int ldres,
    float* __restrict__ C2)
{
    extern __shared__ __align__(128) char sm[];
    uint32_t sbase = smem_u32(sm);

    int tid = threadIdx.x;
    int wid = tid >> 5, lane = tid & 31;
    int laneR = lane >> 2, laneC = lane & 3;
    int warp_m = wid & 1, warp_n = wid >> 1;
    int row0 = blockIdx.y * 128, col0 = blockIdx.x * 128;

    float d[4][4][4];
    #pragma unroll
    for (int i = 0; i < 4; i++)
        #pragma unroll
        for (int j = 0; j < 4; j++)
            #pragma unroll
            for (int u = 0; u < 4; u++) d[i][j][u] = 0.f;

    const int NK = K >> 5;

    issue_tile(sbase, sbase + 16384, A, lda, B, ldb, row0, col0, 0, tid);
    CP_COMMIT();
    issue_tile(sbase + 32768, sbase + 49152, A, lda, B, ldb, row0, col0, 32, tid);
    CP_COMMIT();

    #pragma unroll 1
    for (int kt = 0; kt < NK; kt++) {
        CP_WAIT1();
        __syncthreads();
        if (kt + 2 < NK) {
            int s = (kt + 2) % 3;
            issue_tile(sbase + s * 32768, sbase + s * 32768 + 16384,
                       A, lda, B, ldb, row0, col0, (kt + 2) << 5, tid);
        }
        CP_COMMIT();
        int b = kt % 3;
        compute_tile(sm + b * 32768, sm + b * 32768 + 16384, d, warp_m, warp_n, laneR, laneC);
    }

    #pragma unroll
    for (int mf = 0; mf < 4; mf++) {
        int r = row0 + warp_m * 64 + mf * 16 + laneR;
        #pragma unroll
        for (int nf = 0; nf < 4; nf++) {
            int cc = col0 + warp_n * 32 + nf * 8 + 2 * laneC;
            float2 v0 = make_float2(d[mf][nf][0], d[mf][nf][1]);
            float2 v1 = make_float2(d[mf][nf][2], d[mf][nf][3]);
            if (bias) {
                float2 bv = *(const float2*)(bias + cc);
                v0.x += bv.x; v0.y += bv.y;
                v1.x += bv.x; v1.y += bv.y;
            }
            if (res) {
                float2 r0 = *(const float2*)(res + (size_t)r * ldres + cc);
                float2 r1 = *(const float2*)(res + (size_t)(r + 8) * ldres + cc);
                v0.x += r0.x; v0.y += r0.y;
                v1.x += r1.x; v1.y += r1.y;
            }
            *(float2*)(C + (size_t)r * ldc + cc)       = v0;
            *(float2*)(C + (size_t)(r + 8) * ldc + cc) = v1;
            if (C2) {
                uint2 t0 = make_uint2(f2tf32(v0.x), f2tf32(v0.y));
                uint2 t1 = make_uint2(f2tf32(v1.x), f2tf32(v1.y));
                *(uint2*)(C2 + (size_t)r * ldc + cc)       = t0;
                *(uint2*)(C2 + (size_t)(r + 8) * ldc + cc) = t1;
            }
        }
    }
}

// ---------------- weight convert ------------------------------------------------
__global__ __launch_bounds__(256) void wconv_kernel(
    const float* __restrict__ up, const float* __restrict__ q,
    const float* __restrict__ k,  const float* __restrict__ v,
    const float* __restrict__ dn, const float* __restrict__ fin,
    float* __restrict__ out)
{
    int i = blockIdx.x * 256 + threadIdx.x;
    const float* src; int off;
    if      (i <  524288) { src = up;  off = i; }
    else if (i < 1048576) { src = q;   off = i -  524288; }
    else if (i < 1572864) { src = k;   off = i - 1048576; }
    else if (i < 2097152) { src = v;   off = i - 1572864; }
    else if (i < 2359296) { src = dn;  off = i - 2097152; }
    else                  { src = fin; off = i - 2359296; }
    float4 x = ((const float4*)src)[off];
    uint4 y = make_uint4(f2tf32(x.x), f2tf32(x.y), f2tf32(x.z), f2tf32(x.w));
    ((uint4*)out)[i] = y;
}

// ---------------- V transpose per (b,h): g_v -> g_vT[bh][d][t], tf32-packed ----
__global__ __launch_bounds__(256) void vtrans_kernel(float* __restrict__ vT)
{
    __shared__ float t[32][33];
    int bh = blockIdx.z;
    int b = bh >> 2, h = bh & 3;
    int t0 = blockIdx.x * 32, d0 = blockIdx.y * 32;
    int tx = threadIdx.x & 31, ty = threadIdx.x >> 5;
    #pragma unroll
    for (int j = 0; j < 32; j += 8)
        t[ty + j][tx] = g_v[(size_t)(b * SS + t0 + ty + j) * II + h * DHH + d0 + tx];
    __syncthreads();
    #pragma unroll
    for (int j = 0; j < 32; j += 8)
        vT[((size_t)bh * DHH + d0 + ty + j) * SS + t0 + tx] =
            __uint_as_float(f2tf32(t[tx][ty + j]));
}

// ---------------- LayerNorm over E=512 (stores tf32 bits) ----------------------
__global__ __launch_bounds__(256) void ln_kernel(const float* __restrict__ x,
                                                 const float* __restrict__ g,
                                                 const float* __restrict__ b,
                                                 float* __restrict__ y)
{
    int row = blockIdx.x;
    const float* xr = x + (size_t)row * EE;
    float s = 0.f, s2 = 0.f;
    for (int c = threadIdx.x; c < EE; c += 256) { float v = xr[c]; s += v; s2 += v*v; }
    __shared__ float sh[64];
    for (int o = 16; o; o >>= 1) {
        s  += __shfl_down_sync(0xffffffffu, s,  o);
        s2 += __shfl_down_sync(0xffffffffu, s2, o);
    }
    int wid = threadIdx.x >> 5, lane = threadIdx.x & 31;
    if (lane == 0) { sh[wid] = s; sh[32+wid] = s2; }
    __syncthreads();
    if (threadIdx.x == 0) {
        float ts = 0.f, ts2 = 0.f;
        for (int w = 0; w < 8; w++) { ts += sh[w]; ts2 += sh[32+w]; }
        sh[0] = ts; sh[32] = ts2;
    }
    __syncthreads();
    float mu  = sh[0]  * (1.f/EE);
    float var = sh[32] * (1.f/EE) - mu*mu;
    float rstd = rsqrtf(var + EPS);
    float* yr = y + (size_t)row * EE;
    for (int c = threadIdx.x; c < EE; c += 256)
        yr[c] = __uint_as_float(f2tf32((xr[c] - mu) * rstd * g[c] + b[c]));
}

// ---------------- causal depthwise conv (K=4) + SiLU, 4 channels/thread --------
__global__ __launch_bounds__(256) void conv_silu_kernel(const float* __restrict__ cw,
                                                        const float* __restrict__ cb)
{
    int idx = blockIdx.x * 256 + threadIdx.x;     // [0, BSR*II/4)
    int c4  = (idx & 255) << 2;
    int row = idx >> 8;
    int t   = row & (SS - 1);
    const float* base = g_up + (size_t)row * 2048 + c4;
    float4 acc = *(const float4*)(cb + c4);
    #pragma unroll
    for (int j = 0; j < KKC; j++) {
        int tt = t - (KKC - 1) + j;
        if (tt >= 0) {
            float4 xv = *(const float4*)(base + (j - (KKC - 1)) * 2048);
            float4 wv = *(const float4*)(cw + j * II + c4);
            acc.x = fmaf(xv.x, wv.x, acc.x);
            acc.y = fmaf(xv.y, wv.y, acc.y);
            acc.z = fmaf(xv.z, wv.z, acc.z);
            acc.w = fmaf(xv.w, wv.w, acc.w);
        }
    }
    float4 sv;
    sv.x = acc.x / (1.f + __expf(-acc.x));
    sv.y = acc.y / (1.f + __expf(-acc.y));
    sv.z = acc.z / (1.f + __expf(-acc.z));
    sv.w = acc.w / (1.f + __expf(-acc.w));
    size_t o = (size_t)row * II + c4;
    *(float4*)(g_cact + o) = sv;
    *(uint4*)(g_ca32 + o) = make_uint4(f2tf32(sv.x), f2tf32(sv.y), f2tf32(sv.z), f2tf32(sv.w));
    float4 xm = *(const float4*)base;
    *(uint4*)(g_xm32 + o) = make_uint4(f2tf32(xm.x), f2tf32(xm.y), f2tf32(xm.z), f2tf32(xm.w));
}

// ---------------- gate projections (float4) ------------------------------------
__global__ __launch_bounds__(256) void gates_kernel(const float* __restrict__ wi,
                                                    const float* __restrict__ bi,
                                                    const float* __restrict__ wf,
                                                    const float* __restrict__ bf)
{
    int row = blockIdx.x;
    int tid = threadIdx.x;
    int d = tid << 2;
    size_t base = (size_t)row * II;
    float4 qv = *(const float4*)(g_q + base + d);
    float4 kv = *(const float4*)(g_k + base + d);
    float4 vv = *(const float4*)(g_v + base + d);
    float ai[HH] = {0,0,0,0}, af[HH] = {0,0,0,0};
    #pragma unroll
    for (int j = 0; j < 4; j++) {
        float aq = ((const float*)&qv)[j];
        float ak = ((const float*)&kv)[j];
        float av = ((const float*)&vv)[j];
        float4 wiq = *(const float4*)(wi + (size_t)(d + j) * HH);
        float4 wik = *(const float4*)(wi + (size_t)(II + d + j) * HH);
        float4 wiv = *(const float4*)(wi + (size_t)(2*II + d + j) * HH);
        float4 wfq = *(const float4*)(wf + (size_t)(d + j) * HH);
        float4 wfk = *(const float4*)(wf + (size_t)(II + d + j) * HH);
        float4 wfv = *(const float4*)(wf + (size_t)(2*II + d + j) * HH);
        ai[0] += aq*wiq.x + ak*wik.x + av*wiv.x;
        ai[1] += aq*wiq.y + ak*wik.y + av*wiv.y;
        ai[2] += aq*wiq.z + ak*wik.z + av*wiv.z;
        ai[3] += aq*wiq.w + ak*wik.w + av*wiv.w;
        af[0] += aq*wfq.x + ak*wfk.x + av*wfv.x;
        af[1] += aq*wfq.y + ak*wfk.y + av*wfv.y;
        af[2] += aq*wfq.z + ak*wfk.z + av*wfv.z;
        af[3] += aq*wfq.w + ak*wfk.w + av*wfv.w;
    }
    __shared__ float red[64];
    int lane = threadIdx.x & 31, wid = threadIdx.x >> 5;
    #pragma unroll
    for (int s = 0; s < 8; s++) {
        float x = (s < 4) ? ai[s] : af[s-4];
        for (int o = 16; o; o >>= 1) x += __shfl_down_sync(0xffffffffu, x, o);
        if (lane == 0) red[s * 8 + wid] = x;
    }
    __syncthreads();
    if (threadIdx.x < 64) {
        float x = red[threadIdx.x];
        x += __shfl_down_sync(0xffffffffu, x, 4, 8);
        x += __shfl_down_sync(0xffffffffu, x, 2, 8);
        x += __shfl_down_sync(0xffffffffu, x, 1, 8);
        if ((threadIdx.x & 7) == 0) {
            int s = threadIdx.x >> 3;
            int b = row >> 10, t = row & (SS - 1);
            if (s < 4) g_ipre[((size_t)b*HH + s)     * SS + t] = x + bi[s];
            else       g_fpre[((size_t)b*HH + (s-4)) * SS + t] = x + bf[s-4];
        }
    }
}

// ---------------- gate scan: lfc, u = ipre - lfc, M = runmax u, m = lfc + M -----
__global__ __launch_bounds__(1024) void cumsum_kernel()
{
    int bh = blockIdx.x;
    int t  = threadIdx.x;
    float f  = g_fpre[bh * SS + t];
    float lf = (f > 0.f) ? -log1pf(__expf(-f)) : f - log1pf(__expf(f));
    __shared__ float sc[SS];
    sc[t] = lf;
    __syncthreads();
    for (int off = 1; off < SS; off <<= 1) {
        float v = (t >= off) ? sc[t - off] : 0.f;
        __syncthreads();
        sc[t] += v;
        __syncthreads();
    }
    float lfc = sc[t];
    float u = g_ipre[bh * SS + t] - lfc;
    g_u[bh * SS + t] = u;
    __syncthreads();
    sc[t] = u;
    __syncthreads();
    for (int off = 1; off < SS; off <<= 1) {
        float v = (t >= off) ? sc[t - off] : -1e30f;
        __syncthreads();
        sc[t] = fmaxf(sc[t], v);
        __syncthreads();
    }
    float M = sc[t];
    g_mx[bh * SS + t] = M;
    g_mm[bh * SS + t] = lfc + M;
}

// ---------------- tensor-core causal mLSTM attention (cp.async loads) ----------
#define ATT2_SMEM 214272
__global__ __launch_bounds__(256) void attn2_kernel(const float* __restrict__ vT)
{
    extern __shared__ __align__(128) char sm2[];
    char*  Qs    = sm2;
    char*  Ks    = sm2 + 65536;
    char*  Vs    = sm2 + 131072;
    char*  Ps    = sm2 + 196608;
    float* u_sh  = (float*)(sm2 + 212992);
    float* ss_sh = (float*)(sm2 + 213248);
    uint32_t sb2 = smem_u32(sm2);

    int bh = blockIdx.x;
    int tb = (int)gridDim.y - 1 - (int)blockIdx.y;
    int b = bh >> 2, h = bh & 3;
    int tid = threadIdx.x;
    int wid = tid >> 5, lane = tid & 31;
    int laneR = lane >> 2, laneC = lane & 3;
    int warp_m = wid & 1, warp_n = wid >> 1;
    int t0 = tb * 64;
    size_t qkvbase = ((size_t)b * SS) * II + (size_t)h * DHH;
    const float* vTb = vT + (size_t)bh * DHH * SS;

    // Q tile via cp.async (tf32 bits already; scale folded into epilogue)
    #pragma unroll
    for (int j = 0; j < 16; j++) {
        int i = tid + 256 * j;
        int r = i >> 6, c = i & 63;
        cp_async16(sb2 + r * 1024 + ((c ^ (r & 7)) << 4),
                   g_q32 + qkvbase + (size_t)(t0 + r) * II + (c << 2));
    }
    CP_COMMIT();

    float Mr[4], ssum[4];
    #pragma unroll
    for (int k = 0; k < 4; k++) {
        int row = warp_m * 32 + (k >> 1) * 16 + (k & 1) * 8 + laneR;
        Mr[k] = g_mx[bh * SS + t0 + row];
        ssum[k] = 0.f;
    }

    float o[2][8][4];
    #pragma unroll
    for (int mf = 0; mf < 2; mf++)
        #pragma unroll
        for (int nf = 0; nf < 8; nf++)
            #pragma unroll
            for (int u = 0; u < 4; u++) o[mf][nf][u] = 0.f;

    #pragma unroll 1
    for (int sb = 0; sb <= tb; sb++) {
        int s0 = sb * 64;
        __syncthreads();
        #pragma unroll
        for (int j = 0; j < 16; j++) {
            int i = tid + 256 * j;
            int r = i >> 6, c = i & 63;
            cp_async16(sb2 + 65536 + r * 1024 + ((c ^ (r & 7)) << 4),
                       g_k32 + qkvbase + (size_t)(s0 + r) * II + (c << 2));
        }
        #pragma unroll
        for (int j = 0; j < 16; j++) {
            int i = tid + 256 * j;
            int r = i >> 4, c = i & 15;
            cp_async16(sb2 + 131072 + (r << 8) + ((c ^ (r & 7)) << 4),
                       vTb + (size_t)r * SS + s0 + (c << 2));
        }
        CP_COMMIT();
        if (tid < 16)
            *(float4*)(u_sh + tid * 4) = *(const float4*)(g_u + bh * SS + s0 + tid * 4);
        CP_WAIT0();
        __syncthreads();

        float s8[2][2][4];
        #pragma unroll
        for (int mf = 0; mf < 2; mf++)
            #pragma unroll
            for (int nf = 0; nf < 2; nf++)
                #pragma unroll
                for (int u = 0; u < 4; u++) s8[mf][nf][u] = 0.f;
        {
            const char* aB = Qs + (warp_m * 32 + laneR) * 1024 + laneC * 4;
            const char* bB = Ks + (warp_n * 16 + laneR) * 1024 + laneC * 4;
            #pragma unroll
            for (int ks = 0; ks < 32; ks++) {
                uint32_t c0 = (uint32_t)(((2 * ks)     ^ laneR) << 4);
                uint32_t c1 = (uint32_t)(((2 * ks + 1) ^ laneR) << 4);
                uint32_t a[2][4], bf[2][2];
                #pragma unroll
                for (int mf = 0; mf < 2; mf++) {
                    const char* p = aB + mf * 16384;
                    a[mf][0] = *(const uint32_t*)(p + c0);
                    a[mf][1] = *(const uint32_t*)(p + 8192 + c0);
                    a[mf][2] = *(const uint32_t*)(p + c1);
                    a[mf][3] = *(const uint32_t*)(p + 8192 + c1);
                }
                #pragma unroll
                for (int nf = 0; nf < 2; nf++) {
                    const char* p = bB + nf * 8192;
                    bf[nf][0] = *(const uint32_t*)(p + c0);
                    bf[nf][1] = *(const uint32_t*)(p + c1);
                }
                #pragma unroll
                for (int mf = 0; mf < 2; mf++)
                    #pragma unroll
                    for (int nf = 0; nf < 2; nf++)
                        mma_tf32(s8[mf][nf], a[mf], bf[nf][0], bf[nf][1]);
            }
        }

        bool diag = (sb == tb);
        #pragma unroll
        for (int mf = 0; mf < 2; mf++) {
            #pragma unroll
            for (int e = 0; e < 2; e++) {
                int row = warp_m * 32 + mf * 16 + e * 8 + laneR;
                int tg = t0 + row;
                float M = Mr[mf * 2 + e];
                #pragma unroll
                for (int nf = 0; nf < 2; nf++) {
                    int cb = warp_n * 16 + nf * 8 + 2 * laneC;
                    float d0 = s8[mf][nf][2 * e] * 0.0625f;
                    float d1 = s8[mf][nf][2 * e + 1] * 0.0625f;
                    float w0 = (!diag || (s0 + cb)     <= tg) ? __expf(u_sh[cb]     - M) : 0.f;
                    float w1 = (!diag || (s0 + cb + 1) <= tg) ? __expf(u_sh[cb + 1] - M) : 0.f;
                    uint2 pk = make_uint2(f2tf32(d0 * w0), f2tf32(d1 * w1));
                    ssum[mf * 2 + e] += __uint_as_float(pk.x) + __uint_as_float(pk.y);
                    *(uint2*)(Ps + (row << 8) + (((cb >> 2) ^ (row & 7)) << 4)
                              + ((cb & 3) << 2)) = pk;
                }
            }
        }
        __syncthreads();

        {
            const char* aB = Ps + (warp_m * 32 + laneR) * 256 + laneC * 4;
            const char* bB = Vs + (warp_n * 64 + laneR) * 256 + laneC * 4;
            #pragma unroll
            for (int ks = 0; ks < 8; ks++) {
                uint32_t c0 = (uint32_t)(((2 * ks)     ^ laneR) << 4);
                uint32_t c1 = (uint32_t)(((2 * ks + 1) ^ laneR) << 4);
                uint32_t a[2][4];
                #pragma unroll
                for (int mf = 0; mf < 2; mf++) {
                    const char* p = aB + mf * 4096;
                    a[mf][0] = *(const uint32_t*)(p + c0);
                    a[mf][1] = *(const uint32_t*)(p + 2048 + c0);
                    a[mf][2] = *(const uint32_t*)(p + c1);
                    a[mf][3] = *(const uint32_t*)(p + 2048 + c1);
                }
                #pragma unroll
                for (int nf = 0; nf < 8; nf++) {
                    const char* p = bB + nf * 2048;
                    uint32_t b0 = *(const uint32_t*)(p + c0);
                    uint32_t b1 = *(const uint32_t*)(p + c1);
                    #pragma unroll
                    for (int mf = 0; mf < 2; mf++)
                        mma_tf32(o[mf][nf], a[mf], b0, b1);
                }
            }
        }
    }

    #pragma unroll
    for (int k = 0; k < 4; k++) {
        ssum[k] += __shfl_xor_sync(0xffffffffu, ssum[k], 1);
        ssum[k] += __shfl_xor_sync(0xffffffffu, ssum[k], 2);
    }
    if (laneC == 0) {
        #pragma unroll
        for (int k = 0; k < 4; k++) {
            int row = warp_m * 32 + (k >> 1) * 16 + (k & 1) * 8 + laneR;
            ss_sh[warp_n * 64 + row] = ssum[k];
        }
    }
    __syncthreads();
    float inv[4];
    #pragma unroll
    for (int k = 0; k < 4; k++) {
        int row = warp_m * 32 + (k >> 1) * 16 + (k & 1) * 8 + laneR;
        float tot = ss_sh[row] + ss_sh[64 + row] + ss_sh[128 + row] + ss_sh[192 + row];
        float mm = g_mm[bh * SS + t0 + row];
        inv[k] = 1.f / fmaxf(fabsf(tot), __expf(-mm));
    }
    #pragma unroll
    for (int mf = 0; mf < 2; mf++) {
        int r0 = t0 + warp_m * 32 + mf * 16 + laneR;
        float i0 = inv[mf * 2], i1 = inv[mf * 2 + 1];
        #pragma unroll
        for (int nf = 0; nf < 8; nf++) {
            int c = warp_n * 64 + nf * 8 + 2 * laneC;
            *(float2*)(g_h + qkvbase + (size_t)r0 * II + c) =
                make_float2(o[mf][nf][0] * i0, o[mf][nf][1] * i0);
            *(float2*)(g_h + qkvbase + (size_t)(r0 + 8) * II + c) =
                make_float2(o[mf][nf][2] * i1, o[mf][nf][3] * i1);
        }
    }
}

// ---------------- per-head norm + gate, 1 sync, float4 -------------------------
__global__ __launch_bounds__(256) void headgate_kernel(const float* __restrict__ gn,
                                                       const float* __restrict__ sk)
{
    int row = blockIdx.x;
    int tid = threadIdx.x;
    int wid = tid >> 5, lane = tid & 31;
    int h = wid >> 1;
    int c = h * DHH + (wid & 1) * 128 + lane * 4;
    size_t base = (size_t)row * II;
    float4 v = *(const float4*)(g_h + base + c);
    float s  = v.x + v.y + v.z + v.w;
    float s2 = v.x*v.x + v.y*v.y + v.z*v.z + v.w*v.w;
    for (int o = 16; o; o >>= 1) {
        s  += __shfl_down_sync(0xffffffffu, s,  o);
        s2 += __shfl_down_sync(0xffffffffu, s2, o);
    }
    __shared__ float sh[16];
    if (lane == 0) { sh[wid] = s; sh[8 + wid] = s2; }
    __syncthreads();
    float ts  = sh[h*2]     + sh[h*2 + 1];
    float ts2 = sh[8 + h*2] + sh[8 + h*2 + 1];
    float mu  = ts  * (1.f/DHH);
    float var = ts2 * (1.f/DHH) - mu*mu;
    float rstd = rsqrtf(var + EPS);
    float4 gn4 = *(const float4*)(gn + c);
    float4 sk4 = *(const float4*)(sk + c);
    float4 ca4 = *(const float4*)(g_cact + base + c);
    float4 z4  = *(const float4*)(g_up + (size_t)row * 2048 + II + c);
    float hn[4];
    hn[0] = (v.x - mu) * rstd * gn4.x + sk4.x * ca4.x;
    hn[1] = (v.y - mu) * rstd * gn4.y + sk4.y * ca4.y;
    hn[2] = (v.z - mu) * rstd * gn4.z + sk4.z * ca4.z;
    hn[3] = (v.w - mu) * rstd * gn4.w + sk4.w * ca4.w;
    hn[0] *= z4.x / (1.f + __expf(-z4.x));
    hn[1] *= z4.y / (1.f + __expf(-z4.y));
    hn[2] *= z4.z / (1.f + __expf(-z4.z));
    hn[3] *= z4.w / (1.f + __expf(-z4.w));
    *(uint4*)(g_h + base + c) =
        make_uint4(f2tf32(hn[0]), f2tf32(hn[1]), f2tf32(hn[2]), f2tf32(hn[3]));
}

// ------------------------------- host -----------------------------------------
#define W32_UP(l)   (w32 + (size_t)(l)*1048576)
#define W32_Q(l)    (w32 + 2097152 + (size_t)(l)*1048576)
#define W32_K(l)    (w32 + 4194304 + (size_t)(l)*1048576)
#define W32_V(l)    (w32 + 6291456 + (size_t)(l)*1048576)
#define W32_DOWN(l) (w32 + 8388608 + (size_t)(l)*524288)
#define W32_FIN     (w32 + 9437184)

static inline void launch_gemm(const float* A, int lda, const float* B, int ldb,
                               float* C, int ldc, int M, int N, int K,
                               const float* bias, const float* res, int ldres,
                               float* C2 = nullptr)
{
    dim3 grid(N / 128, M / 128);
    tf32gemm_kernel<<<grid, 256, GEMM_SMEM>>>(A, lda, B, ldb, C, ldc, K,
                                              bias, res, ldres, C2);
}

extern "C" void kernel_launch(void* const* d_in, const int* in_sizes, int n_in,
                              void* d_out, int out_size)
{
    (void)in_sizes; (void)n_in; (void)out_size;
    const float* x      = (const float*)d_in[0];
    const float* ln_g   = (const float*)d_in[1];
    const float* ln_b   = (const float*)d_in[2];
    const float* w_up   = (const float*)d_in[3];
    const float* conv_w = (const float*)d_in[4];
    const float* conv_b = (const float*)d_in[5];
    const float* wq     = (const float*)d_in[6];
    const float* wk     = (const float*)d_in[7];
    const float* wv     = (const float*)d_in[8];
    const float* w_i    = (const float*)d_in[9];
    const float* b_i    = (const float*)d_in[10];
    const float* w_f    = (const float*)d_in[11];
    const float* b_f    = (const float*)d_in[12];
    const float* skip   = (const float*)d_in[13];
    const float* gn_g   = (const float*)d_in[14];
    const float* w_down = (const float*)d_in[15];
    const float* b_down = (const float*)d_in[16];
    const float* w_fin  = (const float*)d_in[17];
    const float* b_fin  = (const float*)d_in[18];

    float *xn, *up, *ca32, *xm32, *hb, *x1, *x132, *w32, *vT, *q32, *k32;
    cudaGetSymbolAddress((void**)&xn,   g_xn);
    cudaGetSymbolAddress((void**)&up,   g_up);
    cudaGetSymbolAddress((void**)&ca32, g_ca32);
    cudaGetSymbolAddress((void**)&xm32, g_xm32);
    cudaGetSymbolAddress((void**)&hb,   g_h);
    cudaGetSymbolAddress((void**)&x1,   g_x1);
    cudaGetSymbolAddress((void**)&x132, g_x132);
    cudaGetSymbolAddress((void**)&w32,  g_w32);
    cudaGetSymbolAddress((void**)&vT,   g_vT);
    cudaGetSymbolAddress((void**)&q32,  g_q32);
    cudaGetSymbolAddress((void**)&k32,  g_k32);
    float *qb, *kb, *vb;
    cudaGetSymbolAddress((void**)&qb, g_q);
    cudaGetSymbolAddress((void**)&kb, g_k);
    cudaGetSymbolAddress((void**)&vb, g_v);

    cudaFuncSetAttribute(tf32gemm_kernel, cudaFuncAttributeMaxDynamicSharedMemorySize,
                         GEMM_SMEM);
    cudaFuncSetAttribute(attn2_kernel, cudaFuncAttributeMaxDynamicSharedMemorySize,
                         ATT2_SMEM);

    wconv_kernel<<<9280, 256>>>(w_up, wq, wk, wv, w_down, w_fin, w32);

    const float* cur = x;
    for (int l = 0; l < 2; l++) {
        ln_kernel<<<BSR, 256>>>(cur, ln_g + l*EE, ln_b + l*EE, xn);
        launch_gemm(xn, EE, W32_UP(l), 2048, up, 2048, BSR, 2048, EE,
                    nullptr, nullptr, 0);
        conv_silu_kernel<<<(BSR*II)/1024, 256>>>(conv_w + l*KKC*II, conv_b + l*II);
        launch_gemm(ca32, II, W32_Q(l), II, qb, II, BSR, II, II, nullptr, nullptr, 0, q32);
        launch_gemm(ca32, II, W32_K(l), II, kb, II, BSR, II, II, nullptr, nullptr, 0, k32);
        launch_gemm(xm32, II, W32_V(l), II, vb, II, BSR, II, II, nullptr, nullptr, 0);
        gates_kernel<<<BSR, 256>>>(w_i + (size_t)l*3*II*HH, b_i + l*HH,
                                   w_f + (size_t)l*3*II*HH, b_f + l*HH);
        cumsum_kernel<<<BB*HH, SS>>>();
        vtrans_kernel<<<dim3(SS/32, DHH/32, BB*HH), 256>>>(vT);
        attn2_kernel<<<dim3(BB*HH, SS/64), 256, ATT2_SMEM>>>(vT);
        headgate_kernel<<<BSR, 256>>>(gn_g + l*II, skip + l*II);
        launch_gemm(hb, II, W32_DOWN(l), EE, x1, EE, BSR, EE, II,
                    b_down + l*EE, cur, EE, x132);
        cur = x1;
    }
    launch_gemm(x132, EE, W32_FIN, 128, (float*)d_out, 128, BSR, 128, EE,
                b_fin, nullptr, 0);
}

// round 7
// speedup vs baseline: 9.3731x; 1.4032x over previous
#include <cuda_runtime.h>
#include <cuda_fp16.h>
#include <cstdint>
#include <math.h>

// Problem dims
#define BB   8
#define SS   1024
#define EE   512
#define II   1024
#define HH   4
#define DHH  256
#define KKC  4
#define BSR  (BB*SS)          // 8192 rows
#define EPS  1e-5f

// ---------------- scratch (static device memory; rewritten every call) ----------
__device__ __half g_xn16[BSR*EE];         // fp16 LN out (up GEMM A)
__device__ float g_up  [BSR*2048];        // x_m = cols [0,1024), z = cols [1024,2048)
__device__ float g_cact[BSR*II];          // fp32 (headgate skip)
__device__ __half g_ca16[BSR*II];         // fp16 (q/k GEMM A)
__device__ __half g_xm16[BSR*II];         // fp16 x_m (v GEMM A)
__device__ float g_q   [BSR*II];
__device__ float g_k   [BSR*II];
__device__ float g_v   [BSR*II];
__device__ float g_q32 [BSR*II];          // tf32 copy of q (attn)
__device__ float g_k32 [BSR*II];          // tf32 copy of k (attn)
__device__ float g_h   [BSR*II];          // attn out (fp32)
__device__ __half g_h16[BSR*II];          // headgate out (down GEMM A)
__device__ float g_x1  [BSR*EE];          // fp32 residual stream
__device__ __half g_x116[BSR*EE];         // fp16 copy (fin GEMM A)
__device__ float g_ipre[BB*HH*SS];
__device__ float g_fpre[BB*HH*SS];
__device__ float g_u   [BB*HH*SS];
__device__ float g_mx  [BB*HH*SS];
__device__ float g_mm  [BB*HH*SS];
__device__ float g_vT  [32*256*1024];     // V^T per (b,h), tf32-packed (32MB)
__device__ __half g_w16[9502720];         // fp16 weights, transposed [N,K] layouts

__device__ __forceinline__ uint32_t f2tf32(float f) {
    uint32_t r;
    asm("cvt.rna.tf32.f32 %0, %1;" : "=r"(r) : "f"(f));
    return r;
}
__device__ __forceinline__ uint32_t smem_u32(const void* p) {
    uint32_t a;
    asm("{ .reg .u64 t; cvta.to.shared.u64 t, %1; cvt.u32.u64 %0, t; }" : "=r"(a) : "l"(p));
    return a;
}
__device__ __forceinline__ void cp_async16(uint32_t dst, const void* src) {
    asm volatile("cp.async.cg.shared.global [%0], [%1], 16;" :: "r"(dst), "l"(src));
}
#define CP_COMMIT() asm volatile("cp.async.commit_group;" ::: "memory")
#define CP_WAIT1()  asm volatile("cp.async.wait_group 1;"  ::: "memory")
#define CP_WAIT0()  asm volatile("cp.async.wait_group 0;"  ::: "memory")

__device__ __forceinline__ void mma_tf32(float* d, const uint32_t* a, uint32_t b0, uint32_t b1) {
    asm volatile("mma.sync.aligned.m16n8k8.row.col.f32.tf32.tf32.f32 "
        "{%0,%1,%2,%3}, {%4,%5,%6,%7}, {%8,%9}, {%0,%1,%2,%3};"
        : "+f"(d[0]), "+f"(d[1]), "+f"(d[2]), "+f"(d[3])
        : "r"(a[0]), "r"(a[1]), "r"(a[2]), "r"(a[3]), "r"(b0), "r"(b1));
}
__device__ __forceinline__ void mma_f16(float* d, const uint32_t* a, uint32_t b0, uint32_t b1) {
    asm volatile("mma.sync.aligned.m16n8k16.row.col.f32.f16.f16.f32 "
        "{%0,%1,%2,%3}, {%4,%5,%6,%7}, {%8,%9}, {%0,%1,%2,%3};"
        : "+f"(d[0]), "+f"(d[1]), "+f"(d[2]), "+f"(d[3])
        : "r"(a[0]), "r"(a[1]), "r"(a[2]), "r"(a[3]), "r"(b0), "r"(b1));
}
#define LDSM_X4(r, addr) \
    asm volatile("ldmatrix.sync.aligned.m8n8.x4.shared.b16 {%0,%1,%2,%3}, [%4];" \
        : "=r"((r)[0]), "=r"((r)[1]), "=r"((r)[2]), "=r"((r)[3]) : "r"(addr))

// ================= fp16 mma.sync GEMM, cp.async 3-stage, ldmatrix ==============
// C[M,N] = A[M,K] @ B[K,N]; A fp16 [M,K], BT fp16 [N,K] (pre-transposed weights).
// CTA tile 128x128, BK=32 halves (64B rows), 8 warps (2m x 4n), warp tile 64x32.
// smem rows 64B; swizzle on 128B line pairs: chunk16B index within line
//   cc = (r&1)*4 + c, store at ((r>>1)*128) + ((cc ^ ((r>>1)&7))<<4).
// Verified conflict-free for cp.async warp stores and all ldmatrix phases.

__device__ __forceinline__ uint32_t sw_off(int r, int c) {
    return (uint32_t)(((r >> 1) << 7) + (((((r & 1) << 2) + c) ^ ((r >> 1) & 7)) << 4));
}

__device__ __forceinline__ void issue_tile16(uint32_t sA, uint32_t sB,
        const __half* A, int lda, const __half* BT, int ldb,
        int row0, int col0, int k0, int tid)
{
    const __half* Ag = A + (size_t)row0 * lda + k0;
    const __half* Bg = BT + (size_t)col0 * ldb + k0;
    #pragma unroll
    for (int j = 0; j < 2; j++) {
        int i = tid + 256 * j;             // 512 chunks: 128 rows x 4
        int r = i >> 2, c = i & 3;
        cp_async16(sA + sw_off(r, c), Ag + (size_t)r * lda + (c << 3));
    }
    #pragma unroll
    for (int j = 0; j < 2; j++) {
        int i = tid + 256 * j;
        int r = i >> 2, c = i & 3;
        cp_async16(sB + sw_off(r, c), Bg + (size_t)r * ldb + (c << 3));
    }
}

__device__ __forceinline__ void compute_tile16(uint32_t sA, uint32_t sB,
        float d[4][4][4], int warp_m, int warp_n, int lane)
{
    // A frag addressing: r0..r3 = (rows0-7,k0-7),(rows8-15,k0-7),(rows0-7,k8-15),(rows8-15,k8-15)
    int aRow = lane & 15, aCs = lane >> 4;
    // B frag: r0..r3 = (n0-7,k0-7),(n0-7,k8-15),(n8-15,k0-7),(n8-15,k8-15)
    int bRow = (lane & 7) | ((lane >> 1) & 8), bCs = (lane >> 3) & 1;
    uint32_t aBase = sA + (uint32_t)(warp_m * 4096) + sw_off(aRow, aCs);
    uint32_t bBase = sB + (uint32_t)(warp_n * 2048) + sw_off(bRow, bCs);
    #pragma unroll
    for (int ks = 0; ks < 2; ks++) {
        uint32_t kx = (uint32_t)(ks << 5);   // chunk +2 == addr ^ 32 (cs in {0,1})
        uint32_t a[4][4], b[2][4];
        #pragma unroll
        for (int mf = 0; mf < 4; mf++)
            LDSM_X4(a[mf], (aBase + mf * 1024) ^ kx);
        LDSM_X4(b[0], bBase ^ kx);
        LDSM_X4(b[1], (bBase + 1024) ^ kx);
        #pragma unroll
        for (int mf = 0; mf < 4; mf++) {
            mma_f16(d[mf][0], a[mf], b[0][0], b[0][1]);
            mma_f16(d[mf][1], a[mf], b[0][2], b[0][3]);
            mma_f16(d[mf][2], a[mf], b[1][0], b[1][1]);
            mma_f16(d[mf][3], a[mf], b[1][2], b[1][3]);
        }
    }
}

#define GEMM_SMEM (3 * 16384)

__global__ __launch_bounds__(256) void hgemm_kernel(
    const __half* __restrict__ A, int lda,
    const __half* __restrict__ BT, int ldb,   // [N,K]
    float* __restrict__ C, int ldc, int K,
    const float* __restrict__ bias,
    const float* __restrict__ res, int ldres,
    float* __restrict__ C2tf, __half* __restrict__ C2h)
{
    extern __shared__ __align__(128) char sm[];
    uint32_t sbase = smem_u32(sm);

    int tid = threadIdx.x;
    int wid = tid >> 5, lane = tid & 31;
    int laneR = lane >> 2, laneC = lane & 3;
    int warp_m = wid & 1, warp_n = wid >> 1;
    int row0 = blockIdx.y * 128, col0 = blockIdx.x * 128;

    float d[4][4][4];
    #pragma unroll
    for (int i = 0; i < 4; i++)
        #pragma unroll
        for (int j = 0; j < 4; j++)
            #pragma unroll
            for (int u = 0; u < 4; u++) d[i][j][u] = 0.f;

    const int NK = K >> 5;

    issue_tile16(sbase, sbase + 8192, A, lda, BT, ldb, row0, col0, 0, tid);
    CP_COMMIT();
    issue_tile16(sbase + 16384, sbase + 24576, A, lda, BT, ldb, row0, col0, 32, tid);
    CP_COMMIT();

    #pragma unroll 1
    for (int kt = 0; kt < NK; kt++) {
        CP_WAIT1();
        __syncthreads();
        if (kt + 2 < NK) {
            uint32_t s = (uint32_t)((kt + 2) % 3) * 16384;
            issue_tile16(sbase + s, sbase + s + 8192,
                         A, lda, BT, ldb, row0, col0, (kt + 2) << 5, tid);
        }
        CP_COMMIT();
        uint32_t b = (uint32_t)(kt % 3) * 16384;
        compute_tile16(sbase + b, sbase + b + 8192, d, warp_m, warp_n, lane);
    }

    #pragma unroll
    for (int mf = 0; mf < 4; mf++) {
        int r = row0 + warp_m * 64 + mf * 16 + laneR;
        #pragma unroll
        for (int nf = 0; nf < 4; nf++) {
            int cc = col0 + warp_n * 32 + nf * 8 + 2 * laneC;
            float2 v0 = make_float2(d[mf][nf][0], d[mf][nf][1]);
            float2 v1 = make_float2(d[mf][nf][2], d[mf][nf][3]);
            if (bias) {
                float2 bv = *(const float2*)(bias + cc);
                v0.x += bv.x; v0.y += bv.y;
                v1.x += bv.x; v1.y += bv.y;
            }
            if (res) {
                float2 r0 = *(const float2*)(res + (size_t)r * ldres + cc);
                float2 r1 = *(const float2*)(res + (size_t)(r + 8) * ldres + cc);
                v0.x += r0.x; v0.y += r0.y;
                v1.x += r1.x; v1.y += r1.y;
            }
            *(float2*)(C + (size_t)r * ldc + cc)       = v0;
            *(float2*)(C + (size_t)(r + 8) * ldc + cc) = v1;
            if (C2tf) {
                *(uint2*)(C2tf + (size_t)r * ldc + cc) =
                    make_uint2(f2tf32(v0.x), f2tf32(v0.y));
                *(uint2*)(C2tf + (size_t)(r + 8) * ldc + cc) =
                    make_uint2(f2tf32(v1.x), f2tf32(v1.y));
            }
            if (C2h) {
                *(__half2*)(C2h + (size_t)r * ldc + cc)       = __floats2half2_rn(v0.x, v0.y);
                *(__half2*)(C2h + (size_t)(r + 8) * ldc + cc) = __floats2half2_rn(v1.x, v1.y);
            }
        }
    }
}

// ---------------- weight transpose+convert: fp32 [K,N] -> fp16 [N,K] -----------
__global__ __launch_bounds__(256) void wtrans_kernel(const float* __restrict__ in,
                                                     __half* __restrict__ out,
                                                     int K, int N)
{
    __shared__ float t[32][33];
    int kb = blockIdx.y * 32, nb = blockIdx.x * 32;
    int tx = threadIdx.x & 31, ty = threadIdx.x >> 5;
    #pragma unroll
    for (int j = 0; j < 32; j += 8)
        t[ty + j][tx] = in[(size_t)(kb + ty + j) * N + nb + tx];
    __syncthreads();
    #pragma unroll
    for (int j = 0; j < 32; j += 8)
        out[(size_t)(nb + ty + j) * K + kb + tx] = __float2half_rn(t[tx][ty + j]);
}

// ---------------- V transpose per (b,h): g_v -> g_vT[bh][d][t], tf32-packed ----
__global__ __launch_bounds__(256) void vtrans_kernel(float* __restrict__ vT)
{
    __shared__ float t[32][33];
    int bh = blockIdx.z;
    int b = bh >> 2, h = bh & 3;
    int t0 = blockIdx.x * 32, d0 = blockIdx.y * 32;
    int tx = threadIdx.x & 31, ty = threadIdx.x >> 5;
    #pragma unroll
    for (int j = 0; j < 32; j += 8)
        t[ty + j][tx] = g_v[(size_t)(b * SS + t0 + ty + j) * II + h * DHH + d0 + tx];
    __syncthreads();
    #pragma unroll
    for (int j = 0; j < 32; j += 8)
        vT[((size_t)bh * DHH + d0 + ty + j) * SS + t0 + tx] =
            __uint_as_float(f2tf32(t[tx][ty + j]));
}

// ---------------- LayerNorm over E=512 (stores fp16) ---------------------------
__global__ __launch_bounds__(256) void ln_kernel(const float* __restrict__ x,
                                                 const float* __restrict__ g,
                                                 const float* __restrict__ b,
                                                 __half* __restrict__ y)
{
    int row = blockIdx.x;
    const float* xr = x + (size_t)row * EE;
    int c2 = threadIdx.x * 2;
    float2 xv = *(const float2*)(xr + c2);
    float s = xv.x + xv.y, s2 = xv.x*xv.x + xv.y*xv.y;
    __shared__ float sh[64];
    for (int o = 16; o; o >>= 1) {
        s  += __shfl_down_sync(0xffffffffu, s,  o);
        s2 += __shfl_down_sync(0xffffffffu, s2, o);
    }
    int wid = threadIdx.x >> 5, lane = threadIdx.x & 31;
    if (lane == 0) { sh[wid] = s; sh[32+wid] = s2; }
    __syncthreads();
    if (threadIdx.x == 0) {
        float ts = 0.f, ts2 = 0.f;
        for (int w = 0; w < 8; w++) { ts += sh[w]; ts2 += sh[32+w]; }
        sh[0] = ts; sh[32] = ts2;
    }
    __syncthreads();
    float mu  = sh[0]  * (1.f/EE);
    float var = sh[32] * (1.f/EE) - mu*mu;
    float rstd = rsqrtf(var + EPS);
    float2 gv = *(const float2*)(g + c2);
    float2 bv = *(const float2*)(b + c2);
    *(__half2*)(y + (size_t)row * EE + c2) =
        __floats2half2_rn((xv.x - mu) * rstd * gv.x + bv.x,
                          (xv.y - mu) * rstd * gv.y + bv.y);
}

// ---------------- causal depthwise conv (K=4) + SiLU, 4 channels/thread --------
__global__ __launch_bounds__(256) void conv_silu_kernel(const float* __restrict__ cw,
                                                        const float* __restrict__ cb)
{
    int idx = blockIdx.x * 256 + threadIdx.x;     // [0, BSR*II/4)
    int c4  = (idx & 255) << 2;
    int row = idx >> 8;
    int t   = row & (SS - 1);
    const float* base = g_up + (size_t)row * 2048 + c4;
    float4 acc = *(const float4*)(cb + c4);
    #pragma unroll
    for (int j = 0; j < KKC; j++) {
        int tt = t - (KKC - 1) + j;
        if (tt >= 0) {
            float4 xv = *(const float4*)(base + (j - (KKC - 1)) * 2048);
            float4 wv = *(const float4*)(cw + j * II + c4);
            acc.x = fmaf(xv.x, wv.x, acc.x);
            acc.y = fmaf(xv.y, wv.y, acc.y);
            acc.z = fmaf(xv.z, wv.z, acc.z);
            acc.w = fmaf(xv.w, wv.w, acc.w);
        }
    }
    float4 sv;
    sv.x = acc.x / (1.f + __expf(-acc.x));
    sv.y = acc.y / (1.f + __expf(-acc.y));
    sv.z = acc.z / (1.f + __expf(-acc.z));
    sv.w = acc.w / (1.f + __expf(-acc.w));
    size_t o = (size_t)row * II + c4;
    *(float4*)(g_cact + o) = sv;
    __half2* p = (__half2*)(g_ca16 + o);
    p[0] = __floats2half2_rn(sv.x, sv.y);
    p[1] = __floats2half2_rn(sv.z, sv.w);
    float4 xm = *(const float4*)base;
    __half2* q = (__half2*)(g_xm16 + o);
    q[0] = __floats2half2_rn(xm.x, xm.y);
    q[1] = __floats2half2_rn(xm.z, xm.w);
}

// ---------------- gate projections (float4) ------------------------------------
__global__ __launch_bounds__(256) void gates_kernel(const float* __restrict__ wi,
                                                    const float* __restrict__ bi,
                                                    const float* __restrict__ wf,
                                                    const float* __restrict__ bf)
{
    int row = blockIdx.x;
    int tid = threadIdx.x;
    int d = tid << 2;
    size_t base = (size_t)row * II;
    float4 qv = *(const float4*)(g_q + base + d);
    float4 kv = *(const float4*)(g_k + base + d);
    float4 vv = *(const float4*)(g_v + base + d);
    float ai[HH] = {0,0,0,0}, af[HH] = {0,0,0,0};
    #pragma unroll
    for (int j = 0; j < 4; j++) {
        float aq = ((const float*)&qv)[j];
        float ak = ((const float*)&kv)[j];
        float av = ((const float*)&vv)[j];
        float4 wiq = *(const float4*)(wi + (size_t)(d + j) * HH);
        float4 wik = *(const float4*)(wi + (size_t)(II + d + j) * HH);
        float4 wiv = *(const float4*)(wi + (size_t)(2*II + d + j) * HH);
        float4 wfq = *(const float4*)(wf + (size_t)(d + j) * HH);
        float4 wfk = *(const float4*)(wf + (size_t)(II + d + j) * HH);
        float4 wfv = *(const float4*)(wf + (size_t)(2*II + d + j) * HH);
        ai[0] += aq*wiq.x + ak*wik.x + av*wiv.x;
        ai[1] += aq*wiq.y + ak*wik.y + av*wiv.y;
        ai[2] += aq*wiq.z + ak*wik.z + av*wiv.z;
        ai[3] += aq*wiq.w + ak*wik.w + av*wiv.w;
        af[0] += aq*wfq.x + ak*wfk.x + av*wfv.x;
        af[1] += aq*wfq.y + ak*wfk.y + av*wfv.y;
        af[2] += aq*wfq.z + ak*wfk.z + av*wfv.z;
        af[3] += aq*wfq.w + ak*wfk.w + av*wfv.w;
    }
    __shared__ float red[64];
    int lane = threadIdx.x & 31, wid = threadIdx.x >> 5;
    #pragma unroll
    for (int s = 0; s < 8; s++) {
        float x = (s < 4) ? ai[s] : af[s-4];
        for (int o = 16; o; o >>= 1) x += __shfl_down_sync(0xffffffffu, x, o);
        if (lane == 0) red[s * 8 + wid] = x;
    }
    __syncthreads();
    if (threadIdx.x < 64) {
        float x = red[threadIdx.x];
        x += __shfl_down_sync(0xffffffffu, x, 4, 8);
        x += __shfl_down_sync(0xffffffffu, x, 2, 8);
        x += __shfl_down_sync(0xffffffffu, x, 1, 8);
        if ((threadIdx.x & 7) == 0) {
            int s = threadIdx.x >> 3;
            int b = row >> 10, t = row & (SS - 1);
            if (s < 4) g_ipre[((size_t)b*HH + s)     * SS + t] = x + bi[s];
            else       g_fpre[((size_t)b*HH + (s-4)) * SS + t] = x + bf[s-4];
        }
    }
}

// ---------------- gate scan: lfc, u = ipre - lfc, M = runmax u, m = lfc + M -----
__global__ __launch_bounds__(1024) void cumsum_kernel()
{
    int bh = blockIdx.x;
    int t  = threadIdx.x;
    float f  = g_fpre[bh * SS + t];
    float lf = (f > 0.f) ? -log1pf(__expf(-f)) : f - log1pf(__expf(f));
    __shared__ float sc[SS];
    sc[t] = lf;
    __syncthreads();
    for (int off = 1; off < SS; off <<= 1) {
        float v = (t >= off) ? sc[t - off] : 0.f;
        __syncthreads();
        sc[t] += v;
        __syncthreads();
    }
    float lfc = sc[t];
    float u = g_ipre[bh * SS + t] - lfc;
    g_u[bh * SS + t] = u;
    __syncthreads();
    sc[t] = u;
    __syncthreads();
    for (int off = 1; off < SS; off <<= 1) {
        float v = (t >= off) ? sc[t - off] : -1e30f;
        __syncthreads();
        sc[t] = fmaxf(sc[t], v);
        __syncthreads();
    }
    float M = sc[t];
    g_mx[bh * SS + t] = M;
    g_mm[bh * SS + t] = lfc + M;
}

// ---------------- tensor-core causal mLSTM attention (tf32, unchanged) ---------
#define ATT2_SMEM 214272
__global__ __launch_bounds__(256) void attn2_kernel(const float* __restrict__ vT)
{
    extern __shared__ __align__(128) char sm2[];
    char*  Qs    = sm2;
    char*  Ks    = sm2 + 65536;
    char*  Vs    = sm2 + 131072;
    char*  Ps    = sm2 + 196608;
    float* u_sh  = (float*)(sm2 + 212992);
    float* ss_sh = (float*)(sm2 + 213248);
    uint32_t sb2 = smem_u32(sm2);

    int bh = blockIdx.x;
    int tb = (int)gridDim.y - 1 - (int)blockIdx.y;
    int b = bh >> 2, h = bh & 3;
    int tid = threadIdx.x;
    int wid = tid >> 5, lane = tid & 31;
    int laneR = lane >> 2, laneC = lane & 3;
    int warp_m = wid & 1, warp_n = wid >> 1;
    int t0 = tb * 64;
    size_t qkvbase = ((size_t)b * SS) * II + (size_t)h * DHH;
    const float* vTb = vT + (size_t)bh * DHH * SS;

    #pragma unroll
    for (int j = 0; j < 16; j++) {
        int i = tid + 256 * j;
        int r = i >> 6, c = i & 63;
        cp_async16(sb2 + r * 1024 + ((c ^ (r & 7)) << 4),
                   g_q32 + qkvbase + (size_t)(t0 + r) * II + (c << 2));
    }
    CP_COMMIT();

    float Mr[4], ssum[4];
    #pragma unroll
    for (int k = 0; k < 4; k++) {
        int row = warp_m * 32 + (k >> 1) * 16 + (k & 1) * 8 + laneR;
        Mr[k] = g_mx[bh * SS + t0 + row];
        ssum[k] = 0.f;
    }

    float o[2][8][4];
    #pragma unroll
    for (int mf = 0; mf < 2; mf++)
        #pragma unroll
        for (int nf = 0; nf < 8; nf++)
            #pragma unroll
            for (int u = 0; u < 4; u++) o[mf][nf][u] = 0.f;

    #pragma unroll 1
    for (int sb = 0; sb <= tb; sb++) {
        int s0 = sb * 64;
        __syncthreads();
        #pragma unroll
        for (int j = 0; j < 16; j++) {
            int i = tid + 256 * j;
            int r = i >> 6, c = i & 63;
            cp_async16(sb2 + 65536 + r * 1024 + ((c ^ (r & 7)) << 4),
                       g_k32 + qkvbase + (size_t)(s0 + r) * II + (c << 2));
        }
        #pragma unroll
        for (int j = 0; j < 16; j++) {
            int i = tid + 256 * j;
            int r = i >> 4, c = i & 15;
            cp_async16(sb2 + 131072 + (r << 8) + ((c ^ (r & 7)) << 4),
                       vTb + (size_t)r * SS + s0 + (c << 2));
        }
        CP_COMMIT();
        if (tid < 16)
            *(float4*)(u_sh + tid * 4) = *(const float4*)(g_u + bh * SS + s0 + tid * 4);
        CP_WAIT0();
        __syncthreads();

        float s8[2][2][4];
        #pragma unroll
        for (int mf = 0; mf < 2; mf++)
            #pragma unroll
            for (int nf = 0; nf < 2; nf++)
                #pragma unroll
                for (int u = 0; u < 4; u++) s8[mf][nf][u] = 0.f;
        {
            const char* aB = Qs + (warp_m * 32 + laneR) * 1024 + laneC * 4;
            const char* bB = Ks + (warp_n * 16 + laneR) * 1024 + laneC * 4;
            #pragma unroll
            for (int ks = 0; ks < 32; ks++) {
                uint32_t c0 = (uint32_t)(((2 * ks)     ^ laneR) << 4);
                uint32_t c1 = (uint32_t)(((2 * ks + 1) ^ laneR) << 4);
                uint32_t a[2][4], bf[2][2];
                #pragma unroll
                for (int mf = 0; mf < 2; mf++) {
                    const char* p = aB + mf * 16384;
                    a[mf][0] = *(const uint32_t*)(p + c0);
                    a[mf][1] = *(const uint32_t*)(p + 8192 + c0);
                    a[mf][2] = *(const uint32_t*)(p + c1);
                    a[mf][3] = *(const uint32_t*)(p + 8192 + c1);
                }
                #pragma unroll
                for (int nf = 0; nf < 2; nf++) {
                    const char* p = bB + nf * 8192;
                    bf[nf][0] = *(const uint32_t*)(p + c0);
                    bf[nf][1] = *(const uint32_t*)(p + c1);
                }
                #pragma unroll
                for (int mf = 0; mf < 2; mf++)
                    #pragma unroll
                    for (int nf = 0; nf < 2; nf++)
                        mma_tf32(s8[mf][nf], a[mf], bf[nf][0], bf[nf][1]);
            }
        }

        bool diag = (sb == tb);
        #pragma unroll
        for (int mf = 0; mf < 2; mf++) {
            #pragma unroll
            for (int e = 0; e < 2; e++) {
                int row = warp_m * 32 + mf * 16 + e * 8 + laneR;
                int tg = t0 + row;
                float M = Mr[mf * 2 + e];
                #pragma unroll
                for (int nf = 0; nf < 2; nf++) {
                    int cb = warp_n * 16 + nf * 8 + 2 * laneC;
                    float d0 = s8[mf][nf][2 * e] * 0.0625f;
                    float d1 = s8[mf][nf][2 * e + 1] * 0.0625f;
                    float w0 = (!diag || (s0 + cb)     <= tg) ? __expf(u_sh[cb]     - M) : 0.f;
                    float w1 = (!diag || (s0 + cb + 1) <= tg) ? __expf(u_sh[cb + 1] - M) : 0.f;
                    uint2 pk = make_uint2(f2tf32(d0 * w0), f2tf32(d1 * w1));
                    ssum[mf * 2 + e] += __uint_as_float(pk.x) + __uint_as_float(pk.y);
                    *(uint2*)(Ps + (row << 8) + (((cb >> 2) ^ (row & 7)) << 4)
                              + ((cb & 3) << 2)) = pk;
                }
            }
        }
        __syncthreads();

        {
            const char* aB = Ps + (warp_m * 32 + laneR) * 256 + laneC * 4;
            const char* bB = Vs + (warp_n * 64 + laneR) * 256 + laneC * 4;
            #pragma unroll
            for (int ks = 0; ks < 8; ks++) {
                uint32_t c0 = (uint32_t)(((2 * ks)     ^ laneR) << 4);
                uint32_t c1 = (uint32_t)(((2 * ks + 1) ^ laneR) << 4);
                uint32_t a[2][4];
                #pragma unroll
                for (int mf = 0; mf < 2; mf++) {
                    const char* p = aB + mf * 4096;
                    a[mf][0] = *(const uint32_t*)(p + c0);
                    a[mf][1] = *(const uint32_t*)(p + 2048 + c0);
                    a[mf][2] = *(const uint32_t*)(p + c1);
                    a[mf][3] = *(const uint32_t*)(p + 2048 + c1);
                }
                #pragma unroll
                for (int nf = 0; nf < 8; nf++) {
                    const char* p = bB + nf * 2048;
                    uint32_t b0 = *(const uint32_t*)(p + c0);
                    uint32_t b1 = *(const uint32_t*)(p + c1);
                    #pragma unroll
                    for (int mf = 0; mf < 2; mf++)
                        mma_tf32(o[mf][nf], a[mf], b0, b1);
                }
            }
        }
    }

    #pragma unroll
    for (int k = 0; k < 4; k++) {
        ssum[k] += __shfl_xor_sync(0xffffffffu, ssum[k], 1);
        ssum[k] += __shfl_xor_sync(0xffffffffu, ssum[k], 2);
    }
    if (laneC == 0) {
        #pragma unroll
        for (int k = 0; k < 4; k++) {
            int row = warp_m * 32 + (k >> 1) * 16 + (k & 1) * 8 + laneR;
            ss_sh[warp_n * 64 + row] = ssum[k];
        }
    }
    __syncthreads();
    float inv[4];
    #pragma unroll
    for (int k = 0; k < 4; k++) {
        int row = warp_m * 32 + (k >> 1) * 16 + (k & 1) * 8 + laneR;
        float tot = ss_sh[row] + ss_sh[64 + row] + ss_sh[128 + row] + ss_sh[192 + row];
        float mm = g_mm[bh * SS + t0 + row];
        inv[k] = 1.f / fmaxf(fabsf(tot), __expf(-mm));
    }
    #pragma unroll
    for (int mf = 0; mf < 2; mf++) {
        int r0 = t0 + warp_m * 32 + mf * 16 + laneR;
        float i0 = inv[mf * 2], i1 = inv[mf * 2 + 1];
        #pragma unroll
        for (int nf = 0; nf < 8; nf++) {
            int c = warp_n * 64 + nf * 8 + 2 * laneC;
            *(float2*)(g_h + qkvbase + (size_t)r0 * II + c) =
                make_float2(o[mf][nf][0] * i0, o[mf][nf][1] * i0);
            *(float2*)(g_h + qkvbase + (size_t)(r0 + 8) * II + c) =
                make_float2(o[mf][nf][2] * i1, o[mf][nf][3] * i1);
        }
    }
}

// ---------------- per-head norm + gate, 1 sync, float4 (stores fp16) -----------
__global__ __launch_bounds__(256) void headgate_kernel(const float* __restrict__ gn,
                                                       const float* __restrict__ sk)
{
    int row = blockIdx.x;
    int tid = threadIdx.x;
    int wid = tid >> 5, lane = tid & 31;
    int h = wid >> 1;
    int c = h * DHH + (wid & 1) * 128 + lane * 4;
    size_t base = (size_t)row * II;
    float4 v = *(const float4*)(g_h + base + c);
    float s  = v.x + v.y + v.z + v.w;
    float s2 = v.x*v.x + v.y*v.y + v.z*v.z + v.w*v.w;
    for (int o = 16; o; o >>= 1) {
        s  += __shfl_down_sync(0xffffffffu, s,  o);
        s2 += __shfl_down_sync(0xffffffffu, s2, o);
    }
    __shared__ float sh[16];
    if (lane == 0) { sh[wid] = s; sh[8 + wid] = s2; }
    __syncthreads();
    float ts  = sh[h*2]     + sh[h*2 + 1];
    float ts2 = sh[8 + h*2] + sh[8 + h*2 + 1];
    float mu  = ts  * (1.f/DHH);
    float var = ts2 * (1.f/DHH) - mu*mu;
    float rstd = rsqrtf(var + EPS);
    float4 gn4 = *(const float4*)(gn + c);
    float4 sk4 = *(const float4*)(sk + c);
    float4 ca4 = *(const float4*)(g_cact + base + c);
    float4 z4  = *(const float4*)(g_up + (size_t)row * 2048 + II + c);
    float hn[4];
    hn[0] = (v.x - mu) * rstd * gn4.x + sk4.x * ca4.x;
    hn[1] = (v.y - mu) * rstd * gn4.y + sk4.y * ca4.y;
    hn[2] = (v.z - mu) * rstd * gn4.z + sk4.z * ca4.z;
    hn[3] = (v.w - mu) * rstd * gn4.w + sk4.w * ca4.w;
    hn[0] *= z4.x / (1.f + __expf(-z4.x));
    hn[1] *= z4.y / (1.f + __expf(-z4.y));
    hn[2] *= z4.z / (1.f + __expf(-z4.z));
    hn[3] *= z4.w / (1.f + __expf(-z4.w));
    __half2* p = (__half2*)(g_h16 + base + c);
    p[0] = __floats2half2_rn(hn[0], hn[1]);
    p[1] = __floats2half2_rn(hn[2], hn[3]);
}

// ------------------------------- host -----------------------------------------
#define W16_UP(l)   (w16 + (size_t)(l)*1048576)
#define W16_Q(l)    (w16 + 2097152 + (size_t)(l)*1048576)
#define W16_K(l)    (w16 + 4194304 + (size_t)(l)*1048576)
#define W16_V(l)    (w16 + 6291456 + (size_t)(l)*1048576)
#define W16_DOWN(l) (w16 + 8388608 + (size_t)(l)*524288)
#define W16_FIN     (w16 + 9437184)

static inline void launch_gemm(const __half* A, int lda, const __half* BT, int ldb,
                               float* C, int ldc, int M, int N, int K,
                               const float* bias, const float* res, int ldres,
                               float* C2tf = nullptr, __half* C2h = nullptr)
{
    dim3 grid(N / 128, M / 128);
    hgemm_kernel<<<grid, 256, GEMM_SMEM>>>(A, lda, BT, ldb, C, ldc, K,
                                           bias, res, ldres, C2tf, C2h);
}

extern "C" void kernel_launch(void* const* d_in, const int* in_sizes, int n_in,
                              void* d_out, int out_size)
{
    (void)in_sizes; (void)n_in; (void)out_size;
    const float* x      = (const float*)d_in[0];
    const float* ln_g   = (const float*)d_in[1];
    const float* ln_b   = (const float*)d_in[2];
    const float* w_up   = (const float*)d_in[3];
    const float* conv_w = (const float*)d_in[4];
    const float* conv_b = (const float*)d_in[5];
    const float* wq     = (const float*)d_in[6];
    const float* wk     = (const float*)d_in[7];
    const float* wv     = (const float*)d_in[8];
    const float* w_i    = (const float*)d_in[9];
    const float* b_i    = (const float*)d_in[10];
    const float* w_f    = (const float*)d_in[11];
    const float* b_f    = (const float*)d_in[12];
    const float* skip   = (const float*)d_in[13];
    const float* gn_g   = (const float*)d_in[14];
    const float* w_down = (const float*)d_in[15];
    const float* b_down = (const float*)d_in[16];
    const float* w_fin  = (const float*)d_in[17];
    const float* b_fin  = (const float*)d_in[18];

    float *up, *x1, *vT, *q32, *k32, *qb, *kb, *vb, *hb;
    __half *xn16, *ca16, *xm16, *h16, *x116, *w16;
    cudaGetSymbolAddress((void**)&xn16, g_xn16);
    cudaGetSymbolAddress((void**)&up,   g_up);
    cudaGetSymbolAddress((void**)&ca16, g_ca16);
    cudaGetSymbolAddress((void**)&xm16, g_xm16);
    cudaGetSymbolAddress((void**)&h16,  g_h16);
    cudaGetSymbolAddress((void**)&hb,   g_h);
    cudaGetSymbolAddress((void**)&x1,   g_x1);
    cudaGetSymbolAddress((void**)&x116, g_x116);
    cudaGetSymbolAddress((void**)&w16,  g_w16);
    cudaGetSymbolAddress((void**)&vT,   g_vT);
    cudaGetSymbolAddress((void**)&q32,  g_q32);
    cudaGetSymbolAddress((void**)&k32,  g_k32);
    cudaGetSymbolAddress((void**)&qb,   g_q);
    cudaGetSymbolAddress((void**)&kb,   g_k);
    cudaGetSymbolAddress((void**)&vb,   g_v);

    cudaFuncSetAttribute(hgemm_kernel, cudaFuncAttributeMaxDynamicSharedMemorySize,
                         GEMM_SMEM);
    cudaFuncSetAttribute(attn2_kernel, cudaFuncAttributeMaxDynamicSharedMemorySize,
                         ATT2_SMEM);

    // ---- weights -> fp16 transposed [N,K] (once per call) ----
    for (int l = 0; l < 2; l++) {
        wtrans_kernel<<<dim3(2048/32, 512/32), 256>>>(w_up  + (size_t)l*512*2048, W16_UP(l),   512, 2048);
        wtrans_kernel<<<dim3(1024/32,1024/32), 256>>>(wq    + (size_t)l*II*II,    W16_Q(l),    1024, 1024);
        wtrans_kernel<<<dim3(1024/32,1024/32), 256>>>(wk    + (size_t)l*II*II,    W16_K(l),    1024, 1024);
        wtrans_kernel<<<dim3(1024/32,1024/32), 256>>>(wv    + (size_t)l*II*II,    W16_V(l),    1024, 1024);
        wtrans_kernel<<<dim3( 512/32,1024/32), 256>>>(w_down+ (size_t)l*II*EE,    W16_DOWN(l), 1024, 512);
    }
    wtrans_kernel<<<dim3(128/32, 512/32), 256>>>(w_fin, W16_FIN, 512, 128);

    const float* cur = x;
    for (int l = 0; l < 2; l++) {
        ln_kernel<<<BSR, 256>>>(cur, ln_g + l*EE, ln_b + l*EE, xn16);
        launch_gemm(xn16, EE, W16_UP(l), EE, up, 2048, BSR, 2048, EE,
                    nullptr, nullptr, 0);
        conv_silu_kernel<<<(BSR*II)/1024, 256>>>(conv_w + l*KKC*II, conv_b + l*II);
        launch_gemm(ca16, II, W16_Q(l), II, qb, II, BSR, II, II,
                    nullptr, nullptr, 0, q32, nullptr);
        launch_gemm(ca16, II, W16_K(l), II, kb, II, BSR, II, II,
                    nullptr, nullptr, 0, k32, nullptr);
        launch_gemm(xm16, II, W16_V(l), II, vb, II, BSR, II, II,
                    nullptr, nullptr, 0);
        gates_kernel<<<BSR, 256>>>(w_i + (size_t)l*3*II*HH, b_i + l*HH,
                                   w_f + (size_t)l*3*II*HH, b_f + l*HH);
        cumsum_kernel<<<BB*HH, SS>>>();
        vtrans_kernel<<<dim3(SS/32, DHH/32, BB*HH), 256>>>(vT);
        attn2_kernel<<<dim3(BB*HH, SS/64), 256, ATT2_SMEM>>>(vT);
        headgate_kernel<<<BSR, 256>>>(gn_g + l*II, skip + l*II);
        launch_gemm(h16, II, W16_DOWN(l), II, x1, EE, BSR, EE, II,
                    b_down + l*EE, cur, EE, nullptr, x116);
        cur = x1;
    }
    // final: (8192,512)@(512,128) + b_fin
    launch_gemm(x116, EE, W16_FIN, EE, (float*)d_out, 128, BSR, 128, EE,
                b_fin, nullptr, 0);
}